// round 5
// baseline (speedup 1.0000x reference)
#include <cuda_runtime.h>

// ---------------- problem constants ----------------
#define NB   2
#define NN   192
#define IND  20
#define DIMD 128
#define HH   8
#define DHH  16
#define C2C  256
#define NSP  (NN*NN)            // 36864
#define C2TOT (NB*C2C*NSP)      // 18874368

// ---------------- scratch (device globals; no allocation allowed) ----------------
__device__ float g_xA[NB*NN*DIMD];
__device__ float g_xB[NB*NN*DIMD];
__device__ float g_cA[NB*DIMD*NN];
__device__ float g_cB[NB*DIMD*NN];
__device__ float g_q[NB*HH*NN*DHH];
__device__ float g_k[NB*HH*NN*DHH];
__device__ float g_v[NB*HH*NN*DHH];
__device__ float g_upd[NB*NN*DIMD];
__device__ float g_G[NB*HH*NSP];
__device__ float g_scale[C2C];
__device__ float g_shift[C2C];
__device__ float g_c2A[C2TOT];   // persistent pair state (post BN+relu)
__device__ float g_c2B[C2TOT];   // conv input scratch (state + seq2pair(c))

// =================================================================
// Stem: x = conv1d(seq^T, conv1_w)^T ; c = conv1d(seq^T, conv2_w)
// block = (n, b), 128 threads (one per out channel d)
// =================================================================
__global__ void k_stem(const float* __restrict__ seq,
                       const float* __restrict__ w1,
                       const float* __restrict__ w2)
{
    int n = blockIdx.x, b = blockIdx.y, d = threadIdx.x;
    __shared__ float s3[3][IND];
    if (d < 3*IND) {
        int r = d / IND, ic = d % IND;
        int nn = n - 1 + r;
        s3[r][ic] = (nn >= 0 && nn < NN) ? seq[(b*NN + nn)*IND + ic] : 0.f;
    }
    __syncthreads();
    float ax = 0.f, ac = 0.f;
    #pragma unroll
    for (int ic = 0; ic < IND; ++ic) {
        #pragma unroll
        for (int r = 0; r < 3; ++r) {
            float v = s3[r][ic];
            ax += v * w1[(d*IND + ic)*3 + r];
            ac += v * w2[(d*IND + ic)*3 + r];
        }
    }
    g_xA[(b*NN + n)*DIMD + d] = ax;
    g_cA[(b*DIMD + d)*NN + n] = ac;
}

// =================================================================
// seq2pair:  addprev=0:  c2A = pair(c_sel)
//            addprev=1:  c2B = c2A + pair(c_sel)
// =================================================================
__global__ void k_pair(int addprev, int csel)
{
    int idx = blockIdx.x * blockDim.x + threadIdx.x;   // exact grid = C2TOT
    int j  = idx % NN;
    int r1 = idx / NN;
    int i  = r1 % NN;
    int r2 = r1 / NN;
    int ch = r2 % C2C;
    int b  = r2 / C2C;
    const float* c = csel ? g_cB : g_cA;
    float pv = (ch < DIMD) ? c[(b*DIMD + ch)*NN + i]
                           : c[(b*DIMD + (ch - DIMD))*NN + j];
    if (addprev) g_c2B[idx] = g_c2A[idx] + pv;
    else         g_c2A[idx] = pv;
}

// =================================================================
// c = relu(bn1(conv1d(c, c1d_w[l])))  — one block per out channel d.
// 384 threads = (b,n). BN stats over all 384 outputs of this channel.
// rd: which buffer holds current c (0=A,1=B); writes the other one.
// =================================================================
__global__ void __launch_bounds__(384)
k_conv1bn(int rd, const float* __restrict__ w,
          const float* __restrict__ gg, const float* __restrict__ bb)
{
    int d = blockIdx.x;
    int t = threadIdx.x;
    int b = t / NN, n = t % NN;
    const float* c  = rd ? g_cB : g_cA;
    float*       co = rd ? g_cA : g_cB;

    __shared__ float srow[2][NN + 2];
    __shared__ float wsh[DIMD*3];
    __shared__ float red[2][12];

    if (t < DIMD*3) wsh[t] = w[d*DIMD*3 + t];
    if (t < 4) srow[t >> 1][(t & 1) ? (NN + 1) : 0] = 0.f;   // halo zeros
    __syncthreads();

    float acc = 0.f;
    for (int e = 0; e < DIMD; ++e) {
        srow[b][n + 1] = c[(b*DIMD + e)*NN + n];
        __syncthreads();
        acc += srow[b][n]     * wsh[e*3 + 0]
             + srow[b][n + 1] * wsh[e*3 + 1]
             + srow[b][n + 2] * wsh[e*3 + 2];
        __syncthreads();
    }

    float s = acc, ss = acc * acc;
    #pragma unroll
    for (int o = 16; o; o >>= 1) {
        s  += __shfl_down_sync(0xffffffffu, s,  o);
        ss += __shfl_down_sync(0xffffffffu, ss, o);
    }
    if (!(t & 31)) { red[0][t >> 5] = s; red[1][t >> 5] = ss; }
    __syncthreads();
    float ts = 0.f, tss = 0.f;
    #pragma unroll
    for (int ww = 0; ww < 12; ++ww) { ts += red[0][ww]; tss += red[1][ww]; }
    float mean = ts * (1.f/384.f);
    float var  = tss * (1.f/384.f) - mean*mean;
    float inv  = rsqrtf(var + 1e-5f);

    float outv = (acc - mean) * inv * gg[d] + bb[d];
    co[(b*DIMD + d)*NN + n] = fmaxf(outv, 0.f);
}

// =================================================================
// x = LN(x + c^T)   block = (n,b), 128 threads
// =================================================================
__global__ void k_ln(int xs, int cs,
                     const float* __restrict__ gg, const float* __restrict__ bb)
{
    int n = blockIdx.x, b = blockIdx.y, d = threadIdx.x;
    float*       x = xs ? g_xB : g_xA;
    const float* c = cs ? g_cB : g_cA;

    float v = x[(b*NN + n)*DIMD + d] + c[(b*DIMD + d)*NN + n];

    __shared__ float red[2][4];
    float s = v, ss = v*v;
    #pragma unroll
    for (int o = 16; o; o >>= 1) {
        s  += __shfl_down_sync(0xffffffffu, s,  o);
        ss += __shfl_down_sync(0xffffffffu, ss, o);
    }
    if (!(d & 31)) { red[0][d >> 5] = s; red[1][d >> 5] = ss; }
    __syncthreads();
    float m   = (red[0][0]+red[0][1]+red[0][2]+red[0][3]) * (1.f/128.f);
    float var = (red[1][0]+red[1][1]+red[1][2]+red[1][3]) * (1.f/128.f) - m*m;
    float inv = rsqrtf(var + 1e-5f);
    x[(b*NN + n)*DIMD + d] = (v - m) * inv * gg[d] + bb[d];
}

// =================================================================
// conv2d 3x3, C2->C2, in = g_c2B, out(raw) = g_c2A.
// CTA: 64 out channels x one full output row (i, all 192 j).
// 256 threads: thread = (og = t&15 -> 4 oc, jg = t>>4 -> 12 j).
// K loop over 32 chunks of 8 input channels x 9 taps.
// =================================================================
__global__ void __launch_bounds__(256, 2)
k_conv2d(const float* __restrict__ w)
{
    int ocblk = blockIdx.x;     // 0..3
    int i     = blockIdx.y;     // 0..191
    int b     = blockIdx.z;     // 0..1
    int t  = threadIdx.x;
    int og = t & 15, jg = t >> 4;
    int ocbase = og * 4, jbase = jg * 12;

    __shared__ float As[8*9*64];     // [ic][tap][oc]
    __shared__ float Bs[8*3*194];    // [ic][r][col],  col = j_in + 1 with zero halo

    float acc[4][12] = {};
    const float* wbase = w + (ocblk*64) * 2304;   // per-oc row: 256*9 contiguous

    #pragma unroll 1
    for (int icc = 0; icc < 32; ++icc) {
        // ---- stage weights (coalesced: 72 contiguous floats per oc) ----
        #pragma unroll
        for (int r = 0; r < 18; ++r) {
            int s = r*256 + t;
            int oc = s / 72, within = s - oc*72;
            int ic = within / 9, tap = within - ic*9;
            As[(ic*9 + tap)*64 + oc] = wbase[oc*2304 + icc*72 + within];
        }
        // ---- stage input rows i-1..i+1 with halo ----
        for (int s = t; s < 8*3*194; s += 256) {
            int col = s % 194;
            int rc  = s / 194;
            int ic  = rc / 3, r = rc - ic*3;
            int row = i - 1 + r;
            float v = 0.f;
            if (row >= 0 && row < NN && col >= 1 && col <= NN)
                v = g_c2B[(((b*C2C) + (icc*8 + ic))*NN + row)*NN + (col - 1)];
            Bs[s] = v;
        }
        __syncthreads();

        #pragma unroll 1
        for (int ic = 0; ic < 8; ++ic) {
            #pragma unroll
            for (int r = 0; r < 3; ++r) {
                float bv[14];
                #pragma unroll
                for (int u = 0; u < 14; ++u)
                    bv[u] = Bs[(ic*3 + r)*194 + jbase + u];
                #pragma unroll
                for (int dj = 0; dj < 3; ++dj) {
                    int tap = r*3 + dj;
                    const float4 a = *(const float4*)&As[(ic*9 + tap)*64 + ocbase];
                    #pragma unroll
                    for (int u = 0; u < 12; ++u) {
                        float bb = bv[u + dj];
                        acc[0][u] += a.x * bb;
                        acc[1][u] += a.y * bb;
                        acc[2][u] += a.z * bb;
                        acc[3][u] += a.w * bb;
                    }
                }
            }
        }
        __syncthreads();
    }

    #pragma unroll
    for (int o = 0; o < 4; ++o) {
        int oc = ocblk*64 + ocbase + o;
        float* op = g_c2A + ((b*C2C + oc)*NN + i)*NN + jbase;
        #pragma unroll
        for (int u = 0; u < 12; u += 4)
            *(float4*)&op[u] = make_float4(acc[o][u], acc[o][u+1], acc[o][u+2], acc[o][u+3]);
    }
}

// =================================================================
// BN2 stats (per out channel over B*N*N) on raw conv output in g_c2A
// =================================================================
__global__ void k_bnstats(const float* __restrict__ gg, const float* __restrict__ bb)
{
    int oc = blockIdx.x, t = threadIdx.x;
    float s = 0.f, ss = 0.f;
    for (int b = 0; b < NB; ++b) {
        const float* p = g_c2A + (b*C2C + oc)*NSP;
        for (int k = t; k < NSP; k += 256) {
            float v = p[k];
            s += v; ss += v*v;
        }
    }
    __shared__ float red[2][8];
    #pragma unroll
    for (int o = 16; o; o >>= 1) {
        s  += __shfl_down_sync(0xffffffffu, s,  o);
        ss += __shfl_down_sync(0xffffffffu, ss, o);
    }
    if (!(t & 31)) { red[0][t >> 5] = s; red[1][t >> 5] = ss; }
    __syncthreads();
    if (t == 0) {
        float ts = 0.f, tss = 0.f;
        #pragma unroll
        for (int ww = 0; ww < 8; ++ww) { ts += red[0][ww]; tss += red[1][ww]; }
        float mean = ts * (1.f / (NB*NSP));
        float var  = tss * (1.f / (NB*NSP)) - mean*mean;
        float inv  = rsqrtf(var + 1e-5f);
        float sc = inv * gg[oc];
        g_scale[oc] = sc;
        g_shift[oc] = bb[oc] - mean * sc;
    }
}

__global__ void k_bnapply()
{
    int idx = blockIdx.x * blockDim.x + threadIdx.x;
    int oc = (idx / NSP) % C2C;
    float v = g_c2A[idx];
    g_c2A[idx] = fmaxf(v * g_scale[oc] + g_shift[oc], 0.f);
}

// =================================================================
// gate logits: G[b,h,i,j] = sum_c c2A[b,c,i,j] * wd[h,c]
// block = (i,b), 192 threads (j)
// =================================================================
__global__ void k_gate(const float* __restrict__ wd)
{
    int i = blockIdx.x, b = blockIdx.y, j = threadIdx.x;
    __shared__ float wsh[C2C*HH];
    for (int s = j; s < C2C*HH; s += NN) {
        int c = s >> 3, h = s & 7;
        wsh[s] = wd[h*C2C + c];
    }
    __syncthreads();
    float acc[HH] = {};
    const float* base = g_c2A + (b*C2C)*NSP + i*NN + j;
    #pragma unroll 4
    for (int c = 0; c < C2C; ++c) {
        float v = base[c*NSP];
        #pragma unroll
        for (int h = 0; h < HH; ++h) acc[h] += v * wsh[c*8 + h];
    }
    #pragma unroll
    for (int h = 0; h < HH; ++h)
        g_G[((b*HH + h)*NN + i)*NN + j] = acc[h];
}

// =================================================================
// Generic 384x128x128 GEMM with relu epilogue.
// out = relu(A @ W^T + bias),  A = x (+ upd optionally)
// outsel: 0/1/2 -> q/k/v in (b,h,n,dh) layout; 3 -> g_xA; 4 -> g_xB; 5 -> dptr
// grid (2 col-tiles, 6 row-tiles), 256 threads, 64x64 tile, 4x4 per thread.
// =================================================================
__global__ void k_gemm64(int asel, int addupd,
                         const float* __restrict__ W,
                         const float* __restrict__ bias,
                         int outsel, float* dptr)
{
    __shared__ float As[32*68];
    __shared__ float Ws[32*68];
    int t = threadIdx.x;
    int tx = t & 15, ty = t >> 4;
    int rowbase = blockIdx.y * 64, colbase = blockIdx.x * 64;

    const float* A = asel ? g_xB : g_xA;
    float* outp; int headed = 0;
    if      (outsel == 0) { outp = g_q; headed = 1; }
    else if (outsel == 1) { outp = g_k; headed = 1; }
    else if (outsel == 2) { outp = g_v; headed = 1; }
    else if (outsel == 3) { outp = g_xA; }
    else if (outsel == 4) { outp = g_xB; }
    else                  { outp = dptr; }

    float acc[4][4] = {};
    for (int kk = 0; kk < 128; kk += 32) {
        #pragma unroll
        for (int r = 0; r < 8; ++r) {
            int s = r*256 + t;
            int row = s >> 5, e = s & 31;
            float v = A[(rowbase + row)*DIMD + kk + e];
            if (addupd) v += g_upd[(rowbase + row)*DIMD + kk + e];
            As[e*68 + row] = v;
            Ws[e*68 + row] = W[(colbase + row)*DIMD + kk + e];
        }
        __syncthreads();
        #pragma unroll
        for (int e = 0; e < 32; ++e) {
            float a0 = As[e*68 + ty*4 + 0], a1 = As[e*68 + ty*4 + 1];
            float a2 = As[e*68 + ty*4 + 2], a3 = As[e*68 + ty*4 + 3];
            float w0 = Ws[e*68 + tx*4 + 0], w1 = Ws[e*68 + tx*4 + 1];
            float w2 = Ws[e*68 + tx*4 + 2], w3 = Ws[e*68 + tx*4 + 3];
            acc[0][0] += a0*w0; acc[0][1] += a0*w1; acc[0][2] += a0*w2; acc[0][3] += a0*w3;
            acc[1][0] += a1*w0; acc[1][1] += a1*w1; acc[1][2] += a1*w2; acc[1][3] += a1*w3;
            acc[2][0] += a2*w0; acc[2][1] += a2*w1; acc[2][2] += a2*w2; acc[2][3] += a2*w3;
            acc[3][0] += a3*w0; acc[3][1] += a3*w1; acc[3][2] += a3*w2; acc[3][3] += a3*w3;
        }
        __syncthreads();
    }

    #pragma unroll
    for (int v = 0; v < 4; ++v) {
        int row = rowbase + ty*4 + v;
        #pragma unroll
        for (int u = 0; u < 4; ++u) {
            int col = colbase + tx*4 + u;
            float r = fmaxf(acc[v][u] + bias[col], 0.f);
            if (headed) {
                int b = row / NN, n = row % NN, h = col >> 4, dh = col & 15;
                outp[((b*HH + h)*NN + n)*DHH + dh] = r;
            } else {
                outp[row*DIMD + col] = r;
            }
        }
    }
}

// =================================================================
// Attention + gate:  block = (i, h, b), 256 threads.
// =================================================================
__global__ void k_attn(const float* __restrict__ mask,
                       const float* __restrict__ wdb)
{
    int i = blockIdx.x, h = blockIdx.y, b = blockIdx.z;
    int t = threadIdx.x;
    int bh = b*HH + h;

    __shared__ float qi[DHH];
    __shared__ float att[NN];
    __shared__ float redm[8];
    __shared__ float reds[8];
    __shared__ float part[16][17];

    if (t < DHH) qi[t] = g_q[(bh*NN + i)*DHH + t];
    __syncthreads();

    float aval = 0.f;
    if (t < NN) {
        const float* kp = g_k + (bh*NN + t)*DHH;
        float s = 0.f;
        #pragma unroll
        for (int d = 0; d < DHH; ++d) s += qi[d] * kp[d];
        aval = s * 0.25f;                // / sqrt(16)
    }
    // row max over all j (pre-mask, matching reference)
    float mval = (t < NN) ? aval : -3e38f;
    #pragma unroll
    for (int o = 16; o; o >>= 1) mval = fmaxf(mval, __shfl_xor_sync(0xffffffffu, mval, o));
    if (!(t & 31)) redm[t >> 5] = mval;
    __syncthreads();
    float mx = redm[0];
    #pragma unroll
    for (int ww = 1; ww < 8; ++ww) mx = fmaxf(mx, redm[ww]);

    float e = (t < NN) ? expf(aval - mx) * mask[b*NN + t] : 0.f;
    float sv = e;
    #pragma unroll
    for (int o = 16; o; o >>= 1) sv += __shfl_xor_sync(0xffffffffu, sv, o);
    if (!(t & 31)) reds[t >> 5] = sv;
    __syncthreads();
    float den = 1e-6f;
    #pragma unroll
    for (int ww = 0; ww < 8; ++ww) den += reds[ww];

    if (t < NN) {
        float gl = g_G[(bh*NN + i)*NN + t] + g_G[(bh*NN + t)*NN + i] + wdb[h];
        float gate = 1.f / (1.f + expf(-gl));
        att[t] = (e / den) * gate;
    }
    __syncthreads();

    // upd[i, h*16+d] = sum_j att[j] * v[j, d]
    int d = t & 15, grp = t >> 4;   // 16 groups x 12 j each
    float p = 0.f;
    #pragma unroll
    for (int jj = 0; jj < 12; ++jj) {
        int j = grp*12 + jj;
        p += att[j] * g_v[(bh*NN + j)*DHH + d];
    }
    part[grp][d] = p;
    __syncthreads();
    if (t < DHH) {
        float s = 0.f;
        #pragma unroll
        for (int gg = 0; gg < 16; ++gg) s += part[gg][t];
        g_upd[(b*NN + i)*DIMD + h*DHH + t] = s;
    }
}

// =================================================================
// host
// =================================================================
extern "C" void kernel_launch(void* const* d_in, const int* in_sizes, int n_in,
                              void* d_out, int out_size)
{
    const float* seq     = (const float*)d_in[0];
    const float* mask    = (const float*)d_in[1];
    const float* conv1_w = (const float*)d_in[2];
    const float* conv2_w = (const float*)d_in[3];
    const float* ln_g    = (const float*)d_in[4];
    const float* ln_b    = (const float*)d_in[5];
    const float* c1d_w   = (const float*)d_in[6];
    const float* bn1_g   = (const float*)d_in[7];
    const float* bn1_b   = (const float*)d_in[8];
    const float* c2d_w   = (const float*)d_in[9];
    const float* bn2_g   = (const float*)d_in[10];
    const float* bn2_b   = (const float*)d_in[11];
    const float* wq_w    = (const float*)d_in[12];
    const float* wq_b    = (const float*)d_in[13];
    const float* wk_w    = (const float*)d_in[14];
    const float* wk_b    = (const float*)d_in[15];
    const float* wv_w    = (const float*)d_in[16];
    const float* wv_b    = (const float*)d_in[17];
    const float* wd_w    = (const float*)d_in[18];
    const float* wd_b    = (const float*)d_in[19];
    const float* wl_w    = (const float*)d_in[20];
    const float* wl_b    = (const float*)d_in[21];
    const float* fc_w    = (const float*)d_in[22];
    const float* fc_b    = (const float*)d_in[23];
    float* out = (float*)d_out;

    k_stem<<<dim3(NN, NB), 128>>>(seq, conv1_w, conv2_w);
    k_pair<<<C2TOT/256, 256>>>(0, 0);              // c2A = seq2pair(c0)

    int xs = 0;
    for (int l = 0; l < 3; ++l) {
        int rd   = l & 1;        // which buffer holds incoming c
        int cnew = rd ^ 1;       // buffer that will hold new c

        k_conv1bn<<<DIMD, 384>>>(rd, c1d_w + l*DIMD*DIMD*3, bn1_g + l*DIMD, bn1_b + l*DIMD);
        k_ln<<<dim3(NN, NB), DIMD>>>(xs, cnew, ln_g + l*DIMD, ln_b + l*DIMD);
        k_pair<<<C2TOT/256, 256>>>(1, cnew);       // c2B = c2A + seq2pair(c_new)
        k_conv2d<<<dim3(4, NN, NB), 256>>>(c2d_w + l*C2C*C2C*9);
        k_bnstats<<<C2C, 256>>>(bn2_g + l*C2C, bn2_b + l*C2C);
        k_bnapply<<<C2TOT/256, 256>>>();
        k_gate<<<dim3(NN, NB), NN>>>(wd_w + l*HH*C2C);
        k_gemm64<<<dim3(2, 6), 256>>>(xs, 0, wq_w + l*DIMD*DIMD, wq_b + l*DIMD, 0, nullptr);
        k_gemm64<<<dim3(2, 6), 256>>>(xs, 0, wk_w + l*DIMD*DIMD, wk_b + l*DIMD, 1, nullptr);
        k_gemm64<<<dim3(2, 6), 256>>>(xs, 0, wv_w + l*DIMD*DIMD, wv_b + l*DIMD, 2, nullptr);
        k_attn<<<dim3(NN, HH, NB), 256>>>(mask, wd_b + l*HH);
        k_gemm64<<<dim3(2, 6), 256>>>(xs, 1, wl_w + l*DIMD*DIMD, wl_b + l*DIMD, xs ? 3 : 4, nullptr);
        xs ^= 1;
    }
    k_gemm64<<<dim3(2, 6), 256>>>(xs, 0, fc_w, fc_b, 5, out);
}

// round 6
// speedup vs baseline: 1.1575x; 1.1575x over previous
#include <cuda_runtime.h>

// ---------------- problem constants ----------------
#define NB   2
#define NN   192
#define IND  20
#define DIMD 128
#define HH   8
#define DHH  16
#define C2C  256
#define NSP  (NN*NN)            // 36864
#define C2TOT (NB*C2C*NSP)      // 18874368

// ---------------- scratch (device globals; no allocation allowed) ----------------
__device__ float g_xA[NB*NN*DIMD];
__device__ float g_xB[NB*NN*DIMD];
__device__ float g_cA[NB*DIMD*NN];
__device__ float g_cB[NB*DIMD*NN];
__device__ float g_q[NB*HH*NN*DHH];
__device__ float g_k[NB*HH*NN*DHH];
__device__ float g_v[NB*HH*NN*DHH];
__device__ float g_upd[NB*NN*DIMD];
__device__ float g_G[NB*HH*NSP];
__device__ float g_scale[C2C];
__device__ float g_shift[C2C];
__device__ float g_c2A[C2TOT];     // persistent pair state (post BN+relu)
__device__ float g_c2X[C2TOT];     // raw conv2d output (pre-BN)
__device__ float2 g_Wsp[C2C*C2C*9]; // split conv2d weights (hi,lo), [ocblk][icc][tap][ic8][oc64]

__device__ __forceinline__ unsigned tf32u(float x) {
    unsigned u; asm("cvt.rna.tf32.f32 %0, %1;" : "=r"(u) : "f"(x)); return u;
}

// =================================================================
// Stem: x = conv1d(seq^T, conv1_w)^T ; c = conv1d(seq^T, conv2_w)
// =================================================================
__global__ void k_stem(const float* __restrict__ seq,
                       const float* __restrict__ w1,
                       const float* __restrict__ w2)
{
    int n = blockIdx.x, b = blockIdx.y, d = threadIdx.x;
    __shared__ float s3[3][IND];
    if (d < 3*IND) {
        int r = d / IND, ic = d % IND;
        int nn = n - 1 + r;
        s3[r][ic] = (nn >= 0 && nn < NN) ? seq[(b*NN + nn)*IND + ic] : 0.f;
    }
    __syncthreads();
    float ax = 0.f, ac = 0.f;
    #pragma unroll
    for (int ic = 0; ic < IND; ++ic) {
        #pragma unroll
        for (int r = 0; r < 3; ++r) {
            float v = s3[r][ic];
            ax += v * w1[(d*IND + ic)*3 + r];
            ac += v * w2[(d*IND + ic)*3 + r];
        }
    }
    g_xA[(b*NN + n)*DIMD + d] = ax;
    g_cA[(b*DIMD + d)*NN + n] = ac;
}

// =================================================================
// init pair state:  c2A = seq2pair(cA)
// =================================================================
__global__ void k_pair0()
{
    int idx = blockIdx.x * blockDim.x + threadIdx.x;   // exact grid = C2TOT
    int j  = idx % NN;
    int r1 = idx / NN;
    int i  = r1 % NN;
    int r2 = r1 / NN;
    int ch = r2 % C2C;
    int b  = r2 / C2C;
    float pv = (ch < DIMD) ? g_cA[(b*DIMD + ch)*NN + i]
                           : g_cA[(b*DIMD + (ch - DIMD))*NN + j];
    g_c2A[idx] = pv;
}

// =================================================================
// c = relu(bn1(conv1d(c, c1d_w[l])))
// =================================================================
__global__ void __launch_bounds__(384)
k_conv1bn(int rd, const float* __restrict__ w,
          const float* __restrict__ gg, const float* __restrict__ bb)
{
    int d = blockIdx.x;
    int t = threadIdx.x;
    int b = t / NN, n = t % NN;
    const float* c  = rd ? g_cB : g_cA;
    float*       co = rd ? g_cA : g_cB;

    __shared__ float srow[2][NN + 2];
    __shared__ float wsh[DIMD*3];
    __shared__ float red[2][12];

    if (t < DIMD*3) wsh[t] = w[d*DIMD*3 + t];
    if (t < 4) srow[t >> 1][(t & 1) ? (NN + 1) : 0] = 0.f;
    __syncthreads();

    float acc = 0.f;
    for (int e = 0; e < DIMD; ++e) {
        srow[b][n + 1] = c[(b*DIMD + e)*NN + n];
        __syncthreads();
        acc += srow[b][n]     * wsh[e*3 + 0]
             + srow[b][n + 1] * wsh[e*3 + 1]
             + srow[b][n + 2] * wsh[e*3 + 2];
        __syncthreads();
    }

    float s = acc, ss = acc * acc;
    #pragma unroll
    for (int o = 16; o; o >>= 1) {
        s  += __shfl_down_sync(0xffffffffu, s,  o);
        ss += __shfl_down_sync(0xffffffffu, ss, o);
    }
    if (!(t & 31)) { red[0][t >> 5] = s; red[1][t >> 5] = ss; }
    __syncthreads();
    float ts = 0.f, tss = 0.f;
    #pragma unroll
    for (int ww = 0; ww < 12; ++ww) { ts += red[0][ww]; tss += red[1][ww]; }
    float mean = ts * (1.f/384.f);
    float var  = tss * (1.f/384.f) - mean*mean;
    float inv  = rsqrtf(var + 1e-5f);

    float outv = (acc - mean) * inv * gg[d] + bb[d];
    co[(b*DIMD + d)*NN + n] = fmaxf(outv, 0.f);
}

// =================================================================
// x = LN(x + c^T)
// =================================================================
__global__ void k_ln(int xs, int cs,
                     const float* __restrict__ gg, const float* __restrict__ bb)
{
    int n = blockIdx.x, b = blockIdx.y, d = threadIdx.x;
    float*       x = xs ? g_xB : g_xA;
    const float* c = cs ? g_cB : g_cA;

    float v = x[(b*NN + n)*DIMD + d] + c[(b*DIMD + d)*NN + n];

    __shared__ float red[2][4];
    float s = v, ss = v*v;
    #pragma unroll
    for (int o = 16; o; o >>= 1) {
        s  += __shfl_down_sync(0xffffffffu, s,  o);
        ss += __shfl_down_sync(0xffffffffu, ss, o);
    }
    if (!(d & 31)) { red[0][d >> 5] = s; red[1][d >> 5] = ss; }
    __syncthreads();
    float m   = (red[0][0]+red[0][1]+red[0][2]+red[0][3]) * (1.f/128.f);
    float var = (red[1][0]+red[1][1]+red[1][2]+red[1][3]) * (1.f/128.f) - m*m;
    float inv = rsqrtf(var + 1e-5f);
    x[(b*NN + n)*DIMD + d] = (v - m) * inv * gg[d] + bb[d];
}

// =================================================================
// split conv2d weights into tf32 (hi,lo), layout [ocblk4][icc32][tap9][ic8][oc64]
// =================================================================
__global__ void k_splitw(const float* __restrict__ w)   // [256][256][9]
{
    int o = blockIdx.x * 256 + threadIdx.x;             // 2304 blocks exact
    int oc64  = o & 63;
    int ic8   = (o >> 6) & 7;
    int tap   = (o >> 9) % 9;
    int icc   = (o / 4608) & 31;
    int ocblk = o / 147456;
    float x = w[(((ocblk*64 + oc64)*C2C) + icc*8 + ic8)*9 + tap];
    float h = __uint_as_float(tf32u(x));
    g_Wsp[o] = make_float2(h, x - h);
}

// =================================================================
// conv2d 3x3 C2->C2 on tensor cores (tf32 hi/lo split, mma.m16n8k8).
// Input is formed on the fly:  in = g_c2A + seq2pair(c_cur).
// Output (raw, pre-BN) -> g_c2X.
// CTA: 64 oc (blockIdx.x) x output row i (blockIdx.y) x batch (blockIdx.z).
// 8 warps: warp tile 32 oc x 48 j  (2 m-frags x 6 n-frags).
// K loop: 32 chunks of 8 input channels; 9 taps per chunk.
// Smem (dynamic, float2 hi/lo):
//   As2[tap9][ic8][oc 68-stride]   (4896 float2)
//   Bs2[r3][ic8][col 196]          (4704 float2), col = j+1 halo
// =================================================================
#define MMA_TF32(c0,c1,c2,c3, A0,A1,A2,A3, B0,B1)                         \
  asm volatile("mma.sync.aligned.m16n8k8.row.col.f32.tf32.tf32.f32 "      \
    "{%0,%1,%2,%3},{%4,%5,%6,%7},{%8,%9},{%0,%1,%2,%3};"                  \
    : "+f"(c0),"+f"(c1),"+f"(c2),"+f"(c3)                                 \
    : "r"(A0),"r"(A1),"r"(A2),"r"(A3),"r"(B0),"r"(B1))

__global__ void __launch_bounds__(256, 2)
k_conv2d_mma(int csel)
{
    extern __shared__ float2 smd[];
    float2* As2 = smd;            // 4896
    float2* Bs2 = smd + 4896;     // 4704

    int ocblk = blockIdx.x;       // 0..3
    int i     = blockIdx.y;       // 0..191
    int b     = blockIdx.z;       // 0..1
    int t = threadIdx.x;
    int w = t >> 5, lane = t & 31;
    int g = lane >> 2, tig = lane & 3;
    int wm = w & 1, wn = w >> 1;

    const float* cc = csel ? g_cB : g_cA;

    float acc[2][6][4];
    #pragma unroll
    for (int m = 0; m < 2; ++m)
        #pragma unroll
        for (int u = 0; u < 6; ++u)
            #pragma unroll
            for (int q = 0; q < 4; ++q) acc[m][u][q] = 0.f;

    const float2* wsrc = g_Wsp + (size_t)ocblk * (32*4608);

    for (int icc = 0; icc < 32; ++icc) {
        // ---- stage split weights: linear copy, 4608 float2 ----
        const float2* wc = wsrc + icc*4608;
        for (int s = t; s < 4608; s += 256) {
            int tap = s >> 9;
            int rem = s & 511;
            int ic  = rem >> 6;
            int oc  = rem & 63;
            As2[(tap*8 + ic)*68 + oc] = wc[s];
        }
        // ---- stage input rows (state + pair term), split to hi/lo ----
        for (int s = t; s < 4704; s += 256) {
            int r   = s / 1568;
            int rem = s - r*1568;
            int ic  = rem / 196;
            int col = rem - ic*196;
            int row = i - 1 + r;
            float2 hv = make_float2(0.f, 0.f);
            if (row >= 0 && row < NN && col >= 1 && col <= NN) {
                int icg = icc*8 + ic;
                int j   = col - 1;
                float v = g_c2A[((size_t)(b*C2C + icg)*NN + row)*NN + j];
                v += (icg < DIMD) ? cc[(b*DIMD + icg)*NN + row]
                                  : cc[(b*DIMD + icg - DIMD)*NN + j];
                float h = __uint_as_float(tf32u(v));
                hv = make_float2(h, v - h);
            }
            Bs2[(r*8 + ic)*196 + col] = hv;
        }
        __syncthreads();

        #pragma unroll
        for (int r = 0; r < 3; ++r) {
            #pragma unroll
            for (int dj = 0; dj < 3; ++dj) {
                int tap = r*3 + dj;
                unsigned ah[2][4], al[2][4];
                #pragma unroll
                for (int m = 0; m < 2; ++m) {
                    int base = wm*32 + m*16 + g;
                    float2 x0 = As2[(tap*8 + tig    )*68 + base    ];
                    float2 x1 = As2[(tap*8 + tig    )*68 + base + 8];
                    float2 x2 = As2[(tap*8 + tig + 4)*68 + base    ];
                    float2 x3 = As2[(tap*8 + tig + 4)*68 + base + 8];
                    ah[m][0] = __float_as_uint(x0.x); al[m][0] = __float_as_uint(x0.y);
                    ah[m][1] = __float_as_uint(x1.x); al[m][1] = __float_as_uint(x1.y);
                    ah[m][2] = __float_as_uint(x2.x); al[m][2] = __float_as_uint(x2.y);
                    ah[m][3] = __float_as_uint(x3.x); al[m][3] = __float_as_uint(x3.y);
                }
                #pragma unroll
                for (int u = 0; u < 6; ++u) {
                    int col = wn*48 + u*8 + g + dj;
                    float2 b0 = Bs2[(r*8 + tig    )*196 + col];
                    float2 b1 = Bs2[(r*8 + tig + 4)*196 + col];
                    unsigned bh0 = __float_as_uint(b0.x), bl0 = __float_as_uint(b0.y);
                    unsigned bh1 = __float_as_uint(b1.x), bl1 = __float_as_uint(b1.y);
                    #pragma unroll
                    for (int m = 0; m < 2; ++m) {
                        float* c = acc[m][u];
                        MMA_TF32(c[0],c[1],c[2],c[3],
                                 ah[m][0],ah[m][1],ah[m][2],ah[m][3], bh0,bh1);
                        MMA_TF32(c[0],c[1],c[2],c[3],
                                 ah[m][0],ah[m][1],ah[m][2],ah[m][3], bl0,bl1);
                        MMA_TF32(c[0],c[1],c[2],c[3],
                                 al[m][0],al[m][1],al[m][2],al[m][3], bh0,bh1);
                    }
                }
            }
        }
        __syncthreads();
    }

    // ---- epilogue: raw conv output to g_c2X ----
    #pragma unroll
    for (int m = 0; m < 2; ++m) {
        int oc0 = ocblk*64 + wm*32 + m*16 + g;
        #pragma unroll
        for (int u = 0; u < 6; ++u) {
            int j = wn*48 + u*8 + 2*tig;
            *(float2*)&g_c2X[((size_t)(b*C2C + oc0    )*NN + i)*NN + j] =
                make_float2(acc[m][u][0], acc[m][u][1]);
            *(float2*)&g_c2X[((size_t)(b*C2C + oc0 + 8)*NN + i)*NN + j] =
                make_float2(acc[m][u][2], acc[m][u][3]);
        }
    }
}

// =================================================================
// BN2 stats on raw conv output g_c2X
// =================================================================
__global__ void k_bnstats(const float* __restrict__ gg, const float* __restrict__ bb)
{
    int oc = blockIdx.x, t = threadIdx.x;
    float s = 0.f, ss = 0.f;
    for (int b = 0; b < NB; ++b) {
        const float* p = g_c2X + (size_t)(b*C2C + oc)*NSP;
        for (int k = t; k < NSP; k += 256) {
            float v = p[k];
            s += v; ss += v*v;
        }
    }
    __shared__ float red[2][8];
    #pragma unroll
    for (int o = 16; o; o >>= 1) {
        s  += __shfl_down_sync(0xffffffffu, s,  o);
        ss += __shfl_down_sync(0xffffffffu, ss, o);
    }
    if (!(t & 31)) { red[0][t >> 5] = s; red[1][t >> 5] = ss; }
    __syncthreads();
    if (t == 0) {
        float ts = 0.f, tss = 0.f;
        #pragma unroll
        for (int ww = 0; ww < 8; ++ww) { ts += red[0][ww]; tss += red[1][ww]; }
        float mean = ts * (1.f / (NB*NSP));
        float var  = tss * (1.f / (NB*NSP)) - mean*mean;
        float inv  = rsqrtf(var + 1e-5f);
        float sc = inv * gg[oc];
        g_scale[oc] = sc;
        g_shift[oc] = bb[oc] - mean * sc;
    }
}

// bnapply: state update  c2A = relu(bn(c2X))
__global__ void k_bnapply()
{
    int idx = blockIdx.x * blockDim.x + threadIdx.x;
    int oc = (idx / NSP) % C2C;
    float v = g_c2X[idx];
    g_c2A[idx] = fmaxf(v * g_scale[oc] + g_shift[oc], 0.f);
}

// =================================================================
// gate logits: G[b,h,i,j] = sum_c c2A[b,c,i,j] * wd[h,c]
// =================================================================
__global__ void k_gate(const float* __restrict__ wd)
{
    int i = blockIdx.x, b = blockIdx.y, j = threadIdx.x;
    __shared__ float wsh[C2C*HH];
    for (int s = j; s < C2C*HH; s += NN) {
        int c = s >> 3, h = s & 7;
        wsh[s] = wd[h*C2C + c];
    }
    __syncthreads();
    float acc[HH] = {};
    const float* base = g_c2A + (size_t)(b*C2C)*NSP + i*NN + j;
    #pragma unroll 4
    for (int c = 0; c < C2C; ++c) {
        float v = base[(size_t)c*NSP];
        #pragma unroll
        for (int h = 0; h < HH; ++h) acc[h] += v * wsh[c*8 + h];
    }
    #pragma unroll
    for (int h = 0; h < HH; ++h)
        g_G[((b*HH + h)*NN + i)*NN + j] = acc[h];
}

// =================================================================
// Generic 384x128x128 GEMM with relu epilogue.
// =================================================================
__global__ void k_gemm64(int asel, int addupd,
                         const float* __restrict__ W,
                         const float* __restrict__ bias,
                         int outsel, float* dptr)
{
    __shared__ float As[32*68];
    __shared__ float Ws[32*68];
    int t = threadIdx.x;
    int tx = t & 15, ty = t >> 4;
    int rowbase = blockIdx.y * 64, colbase = blockIdx.x * 64;

    const float* A = asel ? g_xB : g_xA;
    float* outp; int headed = 0;
    if      (outsel == 0) { outp = g_q; headed = 1; }
    else if (outsel == 1) { outp = g_k; headed = 1; }
    else if (outsel == 2) { outp = g_v; headed = 1; }
    else if (outsel == 3) { outp = g_xA; }
    else if (outsel == 4) { outp = g_xB; }
    else                  { outp = dptr; }

    float acc[4][4] = {};
    for (int kk = 0; kk < 128; kk += 32) {
        #pragma unroll
        for (int r = 0; r < 8; ++r) {
            int s = r*256 + t;
            int row = s >> 5, e = s & 31;
            float v = A[(rowbase + row)*DIMD + kk + e];
            if (addupd) v += g_upd[(rowbase + row)*DIMD + kk + e];
            As[e*68 + row] = v;
            Ws[e*68 + row] = W[(colbase + row)*DIMD + kk + e];
        }
        __syncthreads();
        #pragma unroll
        for (int e = 0; e < 32; ++e) {
            float a0 = As[e*68 + ty*4 + 0], a1 = As[e*68 + ty*4 + 1];
            float a2 = As[e*68 + ty*4 + 2], a3 = As[e*68 + ty*4 + 3];
            float w0 = Ws[e*68 + tx*4 + 0], w1 = Ws[e*68 + tx*4 + 1];
            float w2 = Ws[e*68 + tx*4 + 2], w3 = Ws[e*68 + tx*4 + 3];
            acc[0][0] += a0*w0; acc[0][1] += a0*w1; acc[0][2] += a0*w2; acc[0][3] += a0*w3;
            acc[1][0] += a1*w0; acc[1][1] += a1*w1; acc[1][2] += a1*w2; acc[1][3] += a1*w3;
            acc[2][0] += a2*w0; acc[2][1] += a2*w1; acc[2][2] += a2*w2; acc[2][3] += a2*w3;
            acc[3][0] += a3*w0; acc[3][1] += a3*w1; acc[3][2] += a3*w2; acc[3][3] += a3*w3;
        }
        __syncthreads();
    }

    #pragma unroll
    for (int v = 0; v < 4; ++v) {
        int row = rowbase + ty*4 + v;
        #pragma unroll
        for (int u = 0; u < 4; ++u) {
            int col = colbase + tx*4 + u;
            float r = fmaxf(acc[v][u] + bias[col], 0.f);
            if (headed) {
                int b = row / NN, n = row % NN, h = col >> 4, dh = col & 15;
                outp[((b*HH + h)*NN + n)*DHH + dh] = r;
            } else {
                outp[row*DIMD + col] = r;
            }
        }
    }
}

// =================================================================
// Attention + gate
// =================================================================
__global__ void k_attn(const float* __restrict__ mask,
                       const float* __restrict__ wdb)
{
    int i = blockIdx.x, h = blockIdx.y, b = blockIdx.z;
    int t = threadIdx.x;
    int bh = b*HH + h;

    __shared__ float qi[DHH];
    __shared__ float att[NN];
    __shared__ float redm[8];
    __shared__ float reds[8];
    __shared__ float part[16][17];

    if (t < DHH) qi[t] = g_q[(bh*NN + i)*DHH + t];
    __syncthreads();

    float aval = 0.f;
    if (t < NN) {
        const float* kp = g_k + (bh*NN + t)*DHH;
        float s = 0.f;
        #pragma unroll
        for (int d = 0; d < DHH; ++d) s += qi[d] * kp[d];
        aval = s * 0.25f;
    }
    float mval = (t < NN) ? aval : -3e38f;
    #pragma unroll
    for (int o = 16; o; o >>= 1) mval = fmaxf(mval, __shfl_xor_sync(0xffffffffu, mval, o));
    if (!(t & 31)) redm[t >> 5] = mval;
    __syncthreads();
    float mx = redm[0];
    #pragma unroll
    for (int ww = 1; ww < 8; ++ww) mx = fmaxf(mx, redm[ww]);

    float e = (t < NN) ? expf(aval - mx) * mask[b*NN + t] : 0.f;
    float sv = e;
    #pragma unroll
    for (int o = 16; o; o >>= 1) sv += __shfl_xor_sync(0xffffffffu, sv, o);
    if (!(t & 31)) reds[t >> 5] = sv;
    __syncthreads();
    float den = 1e-6f;
    #pragma unroll
    for (int ww = 0; ww < 8; ++ww) den += reds[ww];

    if (t < NN) {
        float gl = g_G[(bh*NN + i)*NN + t] + g_G[(bh*NN + t)*NN + i] + wdb[h];
        float gate = 1.f / (1.f + expf(-gl));
        att[t] = (e / den) * gate;
    }
    __syncthreads();

    int d = t & 15, grp = t >> 4;
    float p = 0.f;
    #pragma unroll
    for (int jj = 0; jj < 12; ++jj) {
        int j = grp*12 + jj;
        p += att[j] * g_v[(bh*NN + j)*DHH + d];
    }
    part[grp][d] = p;
    __syncthreads();
    if (t < DHH) {
        float s = 0.f;
        #pragma unroll
        for (int gg = 0; gg < 16; ++gg) s += part[gg][t];
        g_upd[(b*NN + i)*DIMD + h*DHH + t] = s;
    }
}

// =================================================================
// host
// =================================================================
extern "C" void kernel_launch(void* const* d_in, const int* in_sizes, int n_in,
                              void* d_out, int out_size)
{
    const float* seq     = (const float*)d_in[0];
    const float* mask    = (const float*)d_in[1];
    const float* conv1_w = (const float*)d_in[2];
    const float* conv2_w = (const float*)d_in[3];
    const float* ln_g    = (const float*)d_in[4];
    const float* ln_b    = (const float*)d_in[5];
    const float* c1d_w   = (const float*)d_in[6];
    const float* bn1_g   = (const float*)d_in[7];
    const float* bn1_b   = (const float*)d_in[8];
    const float* c2d_w   = (const float*)d_in[9];
    const float* bn2_g   = (const float*)d_in[10];
    const float* bn2_b   = (const float*)d_in[11];
    const float* wq_w    = (const float*)d_in[12];
    const float* wq_b    = (const float*)d_in[13];
    const float* wk_w    = (const float*)d_in[14];
    const float* wk_b    = (const float*)d_in[15];
    const float* wv_w    = (const float*)d_in[16];
    const float* wv_b    = (const float*)d_in[17];
    const float* wd_w    = (const float*)d_in[18];
    const float* wd_b    = (const float*)d_in[19];
    const float* wl_w    = (const float*)d_in[20];
    const float* wl_b    = (const float*)d_in[21];
    const float* fc_w    = (const float*)d_in[22];
    const float* fc_b    = (const float*)d_in[23];
    float* out = (float*)d_out;

    const int CONV_SMEM = (4896 + 4704) * sizeof(float2);   // 76800 B
    cudaFuncSetAttribute(k_conv2d_mma, cudaFuncAttributeMaxDynamicSharedMemorySize, CONV_SMEM);

    k_stem<<<dim3(NN, NB), 128>>>(seq, conv1_w, conv2_w);
    k_pair0<<<C2TOT/256, 256>>>();

    int xs = 0;
    for (int l = 0; l < 3; ++l) {
        int rd   = l & 1;        // which buffer holds incoming c
        int cnew = rd ^ 1;       // buffer that will hold new c

        k_conv1bn<<<DIMD, 384>>>(rd, c1d_w + l*DIMD*DIMD*3, bn1_g + l*DIMD, bn1_b + l*DIMD);
        k_ln<<<dim3(NN, NB), DIMD>>>(xs, cnew, ln_g + l*DIMD, ln_b + l*DIMD);
        k_splitw<<<2304, 256>>>(c2d_w + l*C2C*C2C*9);
        k_conv2d_mma<<<dim3(4, NN, NB), 256, CONV_SMEM>>>(cnew);
        k_bnstats<<<C2C, 256>>>(bn2_g + l*C2C, bn2_b + l*C2C);
        k_bnapply<<<C2TOT/256, 256>>>();
        k_gate<<<dim3(NN, NB), NN>>>(wd_w + l*HH*C2C);
        k_gemm64<<<dim3(2, 6), 256>>>(xs, 0, wq_w + l*DIMD*DIMD, wq_b + l*DIMD, 0, nullptr);
        k_gemm64<<<dim3(2, 6), 256>>>(xs, 0, wk_w + l*DIMD*DIMD, wk_b + l*DIMD, 1, nullptr);
        k_gemm64<<<dim3(2, 6), 256>>>(xs, 0, wv_w + l*DIMD*DIMD, wv_b + l*DIMD, 2, nullptr);
        k_attn<<<dim3(NN, HH, NB), 256>>>(mask, wd_b + l*HH);
        k_gemm64<<<dim3(2, 6), 256>>>(xs, 1, wl_w + l*DIMD*DIMD, wl_b + l*DIMD, xs ? 3 : 4, nullptr);
        xs ^= 1;
    }
    k_gemm64<<<dim3(2, 6), 256>>>(xs, 0, fc_w, fc_b, 5, out);
}

// round 8
// speedup vs baseline: 1.6665x; 1.4397x over previous
#include <cuda_runtime.h>
#include <cuda_bf16.h>

// ---------------- problem constants ----------------
#define NB   2
#define NN   192
#define IND  20
#define DIMD 128
#define HH   8
#define DHH  16
#define C2C  256
#define NSP  (NN*NN)            // 36864
#define C2TOT (NB*C2C*NSP)      // 18874368

// ---------------- scratch (device globals; no allocation allowed) ----------------
__device__ float g_xA[NB*NN*DIMD];
__device__ float g_xB[NB*NN*DIMD];
__device__ float g_cA[NB*DIMD*NN];
__device__ float g_cB[NB*DIMD*NN];
__device__ float g_q[NB*HH*NN*DHH];
__device__ float g_k[NB*HH*NN*DHH];
__device__ float g_v[NB*HH*NN*DHH];
__device__ float g_upd[NB*NN*DIMD];
__device__ float g_G[NB*HH*NSP];
__device__ float g_scale[C2C];
__device__ float g_shift[C2C];
__device__ float g_c2A[C2TOT];     // persistent pair state (post BN+relu)
__device__ float g_c2X[C2TOT];     // raw conv2d output (pre-BN)
// split conv2d weights, bf16 hi/lo packed as (ic even | ic odd<<16)
// layout: [ocblk4][icc16][tap9][icpair8][oc64]  (294912 u32 each)
__device__ unsigned g_Wh[C2C*C2C*9/2];
__device__ unsigned g_Wl[C2C*C2C*9/2];

// =================================================================
// Stem: x = conv1d(seq^T, conv1_w)^T ; c = conv1d(seq^T, conv2_w)
// =================================================================
__global__ void k_stem(const float* __restrict__ seq,
                       const float* __restrict__ w1,
                       const float* __restrict__ w2)
{
    int n = blockIdx.x, b = blockIdx.y, d = threadIdx.x;
    __shared__ float s3[3][IND];
    if (d < 3*IND) {
        int r = d / IND, ic = d % IND;
        int nn = n - 1 + r;
        s3[r][ic] = (nn >= 0 && nn < NN) ? seq[(b*NN + nn)*IND + ic] : 0.f;
    }
    __syncthreads();
    float ax = 0.f, ac = 0.f;
    #pragma unroll
    for (int ic = 0; ic < IND; ++ic) {
        #pragma unroll
        for (int r = 0; r < 3; ++r) {
            float v = s3[r][ic];
            ax += v * w1[(d*IND + ic)*3 + r];
            ac += v * w2[(d*IND + ic)*3 + r];
        }
    }
    g_xA[(b*NN + n)*DIMD + d] = ax;
    g_cA[(b*DIMD + d)*NN + n] = ac;
}

// =================================================================
// init pair state:  c2A = seq2pair(cA)
// =================================================================
__global__ void k_pair0()
{
    int idx = blockIdx.x * blockDim.x + threadIdx.x;   // exact grid = C2TOT
    int j  = idx % NN;
    int r1 = idx / NN;
    int i  = r1 % NN;
    int r2 = r1 / NN;
    int ch = r2 % C2C;
    int b  = r2 / C2C;
    float pv = (ch < DIMD) ? g_cA[(b*DIMD + ch)*NN + i]
                           : g_cA[(b*DIMD + (ch - DIMD))*NN + j];
    g_c2A[idx] = pv;
}

// =================================================================
// c = relu(bn1(conv1d(c, c1d_w[l])))
// =================================================================
__global__ void __launch_bounds__(384)
k_conv1bn(int rd, const float* __restrict__ w,
          const float* __restrict__ gg, const float* __restrict__ bb)
{
    int d = blockIdx.x;
    int t = threadIdx.x;
    int b = t / NN, n = t % NN;
    const float* c  = rd ? g_cB : g_cA;
    float*       co = rd ? g_cA : g_cB;

    __shared__ float srow[2][NN + 2];
    __shared__ float wsh[DIMD*3];
    __shared__ float red[2][12];

    if (t < DIMD*3) wsh[t] = w[d*DIMD*3 + t];
    if (t < 4) srow[t >> 1][(t & 1) ? (NN + 1) : 0] = 0.f;
    __syncthreads();

    float acc = 0.f;
    for (int e = 0; e < DIMD; ++e) {
        srow[b][n + 1] = c[(b*DIMD + e)*NN + n];
        __syncthreads();
        acc += srow[b][n]     * wsh[e*3 + 0]
             + srow[b][n + 1] * wsh[e*3 + 1]
             + srow[b][n + 2] * wsh[e*3 + 2];
        __syncthreads();
    }

    float s = acc, ss = acc * acc;
    #pragma unroll
    for (int o = 16; o; o >>= 1) {
        s  += __shfl_down_sync(0xffffffffu, s,  o);
        ss += __shfl_down_sync(0xffffffffu, ss, o);
    }
    if (!(t & 31)) { red[0][t >> 5] = s; red[1][t >> 5] = ss; }
    __syncthreads();
    float ts = 0.f, tss = 0.f;
    #pragma unroll
    for (int ww = 0; ww < 12; ++ww) { ts += red[0][ww]; tss += red[1][ww]; }
    float mean = ts * (1.f/384.f);
    float var  = tss * (1.f/384.f) - mean*mean;
    float inv  = rsqrtf(var + 1e-5f);

    float outv = (acc - mean) * inv * gg[d] + bb[d];
    co[(b*DIMD + d)*NN + n] = fmaxf(outv, 0.f);
}

// =================================================================
// x = LN(x + c^T)
// =================================================================
__global__ void k_ln(int xs, int cs,
                     const float* __restrict__ gg, const float* __restrict__ bb)
{
    int n = blockIdx.x, b = blockIdx.y, d = threadIdx.x;
    float*       x = xs ? g_xB : g_xA;
    const float* c = cs ? g_cB : g_cA;

    float v = x[(b*NN + n)*DIMD + d] + c[(b*DIMD + d)*NN + n];

    __shared__ float red[2][4];
    float s = v, ss = v*v;
    #pragma unroll
    for (int o = 16; o; o >>= 1) {
        s  += __shfl_down_sync(0xffffffffu, s,  o);
        ss += __shfl_down_sync(0xffffffffu, ss, o);
    }
    if (!(d & 31)) { red[0][d >> 5] = s; red[1][d >> 5] = ss; }
    __syncthreads();
    float m   = (red[0][0]+red[0][1]+red[0][2]+red[0][3]) * (1.f/128.f);
    float var = (red[1][0]+red[1][1]+red[1][2]+red[1][3]) * (1.f/128.f) - m*m;
    float inv = rsqrtf(var + 1e-5f);
    x[(b*NN + n)*DIMD + d] = (v - m) * inv * gg[d] + bb[d];
}

// =================================================================
// split conv2d weights -> bf16 hi/lo, packed pairs along ic.
// one thread per u32 (pair of ic).  grid = 1152 x 256 = 294912
// =================================================================
__global__ void k_splitw(const float* __restrict__ w)   // w: [256][256][9]
{
    int o = blockIdx.x * 256 + threadIdx.x;
    int oc    = o & 63;
    int p     = (o >> 6) & 7;
    int tap   = (o >> 9) % 9;
    int icc   = (o / 4608) & 15;
    int ocblk = o / 73728;
    int ocg = ocblk*64 + oc;
    int ic0 = icc*16 + 2*p;
    float x0 = w[(ocg*C2C + ic0    )*9 + tap];
    float x1 = w[(ocg*C2C + ic0 + 1)*9 + tap];
    __nv_bfloat16 h0 = __float2bfloat16(x0);
    __nv_bfloat16 h1 = __float2bfloat16(x1);
    __nv_bfloat16 l0 = __float2bfloat16(x0 - __bfloat162float(h0));
    __nv_bfloat16 l1 = __float2bfloat16(x1 - __bfloat162float(h1));
    g_Wh[o] = ((unsigned)__bfloat16_as_ushort(h1) << 16) | __bfloat16_as_ushort(h0);
    g_Wl[o] = ((unsigned)__bfloat16_as_ushort(l1) << 16) | __bfloat16_as_ushort(l0);
}

// =================================================================
// conv2d 3x3 C2->C2 on tensor cores (bf16 hi/lo split, mma.m16n8k16).
// Input formed on the fly:  in = g_c2A + seq2pair(c_cur).  Raw out -> g_c2X.
// CTA: 64 oc x output row i x batch.  8 warps: 32 oc x 48 j each.
// K loop: 16 chunks of 16 input channels; 9 taps per chunk (k16 per mma).
// Smem (u32):
//   Ah/Al [tap9][icpair8][oc 68-stride]   (4896 each)
//   Bh/Bl [r3][icpair8][col 196]          (4704 each), col = j+1 halo
// =================================================================
#define MMA_BF16(c0,c1,c2,c3, A0,A1,A2,A3, B0,B1)                         \
  asm volatile("mma.sync.aligned.m16n8k16.row.col.f32.bf16.bf16.f32 "     \
    "{%0,%1,%2,%3},{%4,%5,%6,%7},{%8,%9},{%0,%1,%2,%3};"                  \
    : "+f"(c0),"+f"(c1),"+f"(c2),"+f"(c3)                                 \
    : "r"(A0),"r"(A1),"r"(A2),"r"(A3),"r"(B0),"r"(B1))

__global__ void __launch_bounds__(256, 2)
k_conv2d_mma(int csel)
{
    extern __shared__ unsigned smu[];
    unsigned* Ah = smu;             // 4896
    unsigned* Al = smu + 4896;      // 4896
    unsigned* Bh = smu + 9792;      // 4704
    unsigned* Bl = smu + 14496;     // 4704

    int ocblk = blockIdx.x;       // 0..3
    int i     = blockIdx.y;       // 0..191
    int b     = blockIdx.z;       // 0..1
    int t = threadIdx.x;
    int w = t >> 5, lane = t & 31;
    int g = lane >> 2, tig = lane & 3;
    int wm = w & 1, wn = w >> 1;

    const float* cc = csel ? g_cB : g_cA;

    float acc[2][6][4];
    #pragma unroll
    for (int m = 0; m < 2; ++m)
        #pragma unroll
        for (int u = 0; u < 6; ++u)
            #pragma unroll
            for (int q = 0; q < 4; ++q) acc[m][u][q] = 0.f;

    const unsigned* whsrc = g_Wh + ocblk*73728;
    const unsigned* wlsrc = g_Wl + ocblk*73728;

    for (int icc = 0; icc < 16; ++icc) {
        // ---- stage split weights (linear copy, 4608 u32 each) ----
        #pragma unroll
        for (int q = 0; q < 18; ++q) {
            int s = q*256 + t;
            int tap = s >> 9, rem = s & 511;
            int p = rem >> 6, oc = rem & 63;
            int d = (tap*8 + p)*68 + oc;
            Ah[d] = whsrc[icc*4608 + s];
            Al[d] = wlsrc[icc*4608 + s];
        }
        // ---- stage input rows (state + pair term), split to bf16 hi/lo ----
        for (int s = t; s < 9408; s += 256) {
            int r   = s / 3136;
            int rem = s - r*3136;
            int ic  = rem / 196;
            int col = rem - ic*196;
            int row = i - 1 + r;
            float v = 0.f;
            if (row >= 0 && row < NN && col >= 1 && col <= NN) {
                int icg = icc*16 + ic;
                int j   = col - 1;
                v = g_c2A[((size_t)(b*C2C + icg)*NN + row)*NN + j]
                  + ((icg < DIMD) ? cc[(b*DIMD + icg)*NN + row]
                                  : cc[(b*DIMD + icg - DIMD)*NN + j]);
            }
            __nv_bfloat16 h = __float2bfloat16(v);
            __nv_bfloat16 l = __float2bfloat16(v - __bfloat162float(h));
            int d2 = ((r*8 + (ic >> 1))*196 + col)*2 + (ic & 1);
            ((unsigned short*)Bh)[d2] = __bfloat16_as_ushort(h);
            ((unsigned short*)Bl)[d2] = __bfloat16_as_ushort(l);
        }
        __syncthreads();

        #pragma unroll
        for (int r = 0; r < 3; ++r) {
            #pragma unroll
            for (int dj = 0; dj < 3; ++dj) {
                int tap = r*3 + dj;
                unsigned ah[2][4], al[2][4];
                #pragma unroll
                for (int m = 0; m < 2; ++m) {
                    int mb = wm*32 + m*16 + g;
                    ah[m][0] = Ah[(tap*8 + tig    )*68 + mb    ];
                    ah[m][1] = Ah[(tap*8 + tig    )*68 + mb + 8];
                    ah[m][2] = Ah[(tap*8 + tig + 4)*68 + mb    ];
                    ah[m][3] = Ah[(tap*8 + tig + 4)*68 + mb + 8];
                    al[m][0] = Al[(tap*8 + tig    )*68 + mb    ];
                    al[m][1] = Al[(tap*8 + tig    )*68 + mb + 8];
                    al[m][2] = Al[(tap*8 + tig + 4)*68 + mb    ];
                    al[m][3] = Al[(tap*8 + tig + 4)*68 + mb + 8];
                }
                #pragma unroll
                for (int u = 0; u < 6; ++u) {
                    int col = wn*48 + u*8 + g + dj;
                    unsigned bh0 = Bh[(r*8 + tig    )*196 + col];
                    unsigned bh1 = Bh[(r*8 + tig + 4)*196 + col];
                    unsigned bl0 = Bl[(r*8 + tig    )*196 + col];
                    unsigned bl1 = Bl[(r*8 + tig + 4)*196 + col];
                    #pragma unroll
                    for (int m = 0; m < 2; ++m) {
                        float* c = acc[m][u];
                        MMA_BF16(c[0],c[1],c[2],c[3],
                                 ah[m][0],ah[m][1],ah[m][2],ah[m][3], bh0,bh1);
                        MMA_BF16(c[0],c[1],c[2],c[3],
                                 ah[m][0],ah[m][1],ah[m][2],ah[m][3], bl0,bl1);
                        MMA_BF16(c[0],c[1],c[2],c[3],
                                 al[m][0],al[m][1],al[m][2],al[m][3], bh0,bh1);
                    }
                }
            }
        }
        __syncthreads();
    }

    // ---- epilogue: raw conv output to g_c2X ----
    #pragma unroll
    for (int m = 0; m < 2; ++m) {
        int oc0 = ocblk*64 + wm*32 + m*16 + g;
        #pragma unroll
        for (int u = 0; u < 6; ++u) {
            int j = wn*48 + u*8 + 2*tig;
            *(float2*)&g_c2X[((size_t)(b*C2C + oc0    )*NN + i)*NN + j] =
                make_float2(acc[m][u][0], acc[m][u][1]);
            *(float2*)&g_c2X[((size_t)(b*C2C + oc0 + 8)*NN + i)*NN + j] =
                make_float2(acc[m][u][2], acc[m][u][3]);
        }
    }
}

// =================================================================
// BN2 stats on raw conv output g_c2X
// =================================================================
__global__ void k_bnstats(const float* __restrict__ gg, const float* __restrict__ bb)
{
    int oc = blockIdx.x, t = threadIdx.x;
    float s = 0.f, ss = 0.f;
    for (int b = 0; b < NB; ++b) {
        const float* p = g_c2X + (size_t)(b*C2C + oc)*NSP;
        for (int k = t; k < NSP; k += 256) {
            float v = p[k];
            s += v; ss += v*v;
        }
    }
    __shared__ float red[2][8];
    #pragma unroll
    for (int o = 16; o; o >>= 1) {
        s  += __shfl_down_sync(0xffffffffu, s,  o);
        ss += __shfl_down_sync(0xffffffffu, ss, o);
    }
    if (!(t & 31)) { red[0][t >> 5] = s; red[1][t >> 5] = ss; }
    __syncthreads();
    if (t == 0) {
        float ts = 0.f, tss = 0.f;
        #pragma unroll
        for (int ww = 0; ww < 8; ++ww) { ts += red[0][ww]; tss += red[1][ww]; }
        float mean = ts * (1.f / (NB*NSP));
        float var  = tss * (1.f / (NB*NSP)) - mean*mean;
        float inv  = rsqrtf(var + 1e-5f);
        float sc = inv * gg[oc];
        g_scale[oc] = sc;
        g_shift[oc] = bb[oc] - mean * sc;
    }
}

// bnapply: state update  c2A = relu(bn(c2X))
__global__ void k_bnapply()
{
    int idx = blockIdx.x * blockDim.x + threadIdx.x;
    int oc = (idx / NSP) % C2C;
    float v = g_c2X[idx];
    g_c2A[idx] = fmaxf(v * g_scale[oc] + g_shift[oc], 0.f);
}

// =================================================================
// gate logits: G[b,h,i,j] = sum_c c2A[b,c,i,j] * wd[h,c]
// =================================================================
__global__ void k_gate(const float* __restrict__ wd)
{
    int i = blockIdx.x, b = blockIdx.y, j = threadIdx.x;
    __shared__ float wsh[C2C*HH];
    for (int s = j; s < C2C*HH; s += NN) {
        int c = s >> 3, h = s & 7;
        wsh[s] = wd[h*C2C + c];
    }
    __syncthreads();
    float acc[HH] = {};
    const float* base = g_c2A + (size_t)(b*C2C)*NSP + i*NN + j;
    #pragma unroll 4
    for (int c = 0; c < C2C; ++c) {
        float v = base[(size_t)c*NSP];
        #pragma unroll
        for (int h = 0; h < HH; ++h) acc[h] += v * wsh[c*8 + h];
    }
    #pragma unroll
    for (int h = 0; h < HH; ++h)
        g_G[((b*HH + h)*NN + i)*NN + j] = acc[h];
}

// =================================================================
// Generic 384x128x128 GEMM with relu epilogue.
// =================================================================
__global__ void k_gemm64(int asel, int addupd,
                         const float* __restrict__ W,
                         const float* __restrict__ bias,
                         int outsel, float* dptr)
{
    __shared__ float As[32*68];
    __shared__ float Ws[32*68];
    int t = threadIdx.x;
    int tx = t & 15, ty = t >> 4;
    int rowbase = blockIdx.y * 64, colbase = blockIdx.x * 64;

    const float* A = asel ? g_xB : g_xA;
    float* outp; int headed = 0;
    if      (outsel == 0) { outp = g_q; headed = 1; }
    else if (outsel == 1) { outp = g_k; headed = 1; }
    else if (outsel == 2) { outp = g_v; headed = 1; }
    else if (outsel == 3) { outp = g_xA; }
    else if (outsel == 4) { outp = g_xB; }
    else                  { outp = dptr; }

    float acc[4][4] = {};
    for (int kk = 0; kk < 128; kk += 32) {
        #pragma unroll
        for (int r = 0; r < 8; ++r) {
            int s = r*256 + t;
            int row = s >> 5, e = s & 31;
            float v = A[(rowbase + row)*DIMD + kk + e];
            if (addupd) v += g_upd[(rowbase + row)*DIMD + kk + e];
            As[e*68 + row] = v;
            Ws[e*68 + row] = W[(colbase + row)*DIMD + kk + e];
        }
        __syncthreads();
        #pragma unroll
        for (int e = 0; e < 32; ++e) {
            float a0 = As[e*68 + ty*4 + 0], a1 = As[e*68 + ty*4 + 1];
            float a2 = As[e*68 + ty*4 + 2], a3 = As[e*68 + ty*4 + 3];
            float w0 = Ws[e*68 + tx*4 + 0], w1 = Ws[e*68 + tx*4 + 1];
            float w2 = Ws[e*68 + tx*4 + 2], w3 = Ws[e*68 + tx*4 + 3];
            acc[0][0] += a0*w0; acc[0][1] += a0*w1; acc[0][2] += a0*w2; acc[0][3] += a0*w3;
            acc[1][0] += a1*w0; acc[1][1] += a1*w1; acc[1][2] += a1*w2; acc[1][3] += a1*w3;
            acc[2][0] += a2*w0; acc[2][1] += a2*w1; acc[2][2] += a2*w2; acc[2][3] += a2*w3;
            acc[3][0] += a3*w0; acc[3][1] += a3*w1; acc[3][2] += a3*w2; acc[3][3] += a3*w3;
        }
        __syncthreads();
    }

    #pragma unroll
    for (int v = 0; v < 4; ++v) {
        int row = rowbase + ty*4 + v;
        #pragma unroll
        for (int u = 0; u < 4; ++u) {
            int col = colbase + tx*4 + u;
            float r = fmaxf(acc[v][u] + bias[col], 0.f);
            if (headed) {
                int b = row / NN, n = row % NN, h = col >> 4, dh = col & 15;
                outp[((b*HH + h)*NN + n)*DHH + dh] = r;
            } else {
                outp[row*DIMD + col] = r;
            }
        }
    }
}

// =================================================================
// Attention + gate
// =================================================================
__global__ void k_attn(const float* __restrict__ mask,
                       const float* __restrict__ wdb)
{
    int i = blockIdx.x, h = blockIdx.y, b = blockIdx.z;
    int t = threadIdx.x;
    int bh = b*HH + h;

    __shared__ float qi[DHH];
    __shared__ float att[NN];
    __shared__ float redm[8];
    __shared__ float reds[8];
    __shared__ float part[16][17];

    if (t < DHH) qi[t] = g_q[(bh*NN + i)*DHH + t];
    __syncthreads();

    float aval = 0.f;
    if (t < NN) {
        const float* kp = g_k + (bh*NN + t)*DHH;
        float s = 0.f;
        #pragma unroll
        for (int d = 0; d < DHH; ++d) s += qi[d] * kp[d];
        aval = s * 0.25f;
    }
    float mval = (t < NN) ? aval : -3e38f;
    #pragma unroll
    for (int o = 16; o; o >>= 1) mval = fmaxf(mval, __shfl_xor_sync(0xffffffffu, mval, o));
    if (!(t & 31)) redm[t >> 5] = mval;
    __syncthreads();
    float mx = redm[0];
    #pragma unroll
    for (int ww = 1; ww < 8; ++ww) mx = fmaxf(mx, redm[ww]);

    float e = (t < NN) ? expf(aval - mx) * mask[b*NN + t] : 0.f;
    float sv = e;
    #pragma unroll
    for (int o = 16; o; o >>= 1) sv += __shfl_xor_sync(0xffffffffu, sv, o);
    if (!(t & 31)) reds[t >> 5] = sv;
    __syncthreads();
    float den = 1e-6f;
    #pragma unroll
    for (int ww = 0; ww < 8; ++ww) den += reds[ww];

    if (t < NN) {
        float gl = g_G[(bh*NN + i)*NN + t] + g_G[(bh*NN + t)*NN + i] + wdb[h];
        float gate = 1.f / (1.f + expf(-gl));
        att[t] = (e / den) * gate;
    }
    __syncthreads();

    int d = t & 15, grp = t >> 4;
    float p = 0.f;
    #pragma unroll
    for (int jj = 0; jj < 12; ++jj) {
        int j = grp*12 + jj;
        p += att[j] * g_v[(bh*NN + j)*DHH + d];
    }
    part[grp][d] = p;
    __syncthreads();
    if (t < DHH) {
        float s = 0.f;
        #pragma unroll
        for (int gg = 0; gg < 16; ++gg) s += part[gg][t];
        g_upd[(b*NN + i)*DIMD + h*DHH + t] = s;
    }
}

// =================================================================
// host
// =================================================================
extern "C" void kernel_launch(void* const* d_in, const int* in_sizes, int n_in,
                              void* d_out, int out_size)
{
    const float* seq     = (const float*)d_in[0];
    const float* mask    = (const float*)d_in[1];
    const float* conv1_w = (const float*)d_in[2];
    const float* conv2_w = (const float*)d_in[3];
    const float* ln_g    = (const float*)d_in[4];
    const float* ln_b    = (const float*)d_in[5];
    const float* c1d_w   = (const float*)d_in[6];
    const float* bn1_g   = (const float*)d_in[7];
    const float* bn1_b   = (const float*)d_in[8];
    const float* c2d_w   = (const float*)d_in[9];
    const float* bn2_g   = (const float*)d_in[10];
    const float* bn2_b   = (const float*)d_in[11];
    const float* wq_w    = (const float*)d_in[12];
    const float* wq_b    = (const float*)d_in[13];
    const float* wk_w    = (const float*)d_in[14];
    const float* wk_b    = (const float*)d_in[15];
    const float* wv_w    = (const float*)d_in[16];
    const float* wv_b    = (const float*)d_in[17];
    const float* wd_w    = (const float*)d_in[18];
    const float* wd_b    = (const float*)d_in[19];
    const float* wl_w    = (const float*)d_in[20];
    const float* wl_b    = (const float*)d_in[21];
    const float* fc_w    = (const float*)d_in[22];
    const float* fc_b    = (const float*)d_in[23];
    float* out = (float*)d_out;

    const int CONV_SMEM = 19200 * sizeof(unsigned);   // 76800 B
    cudaFuncSetAttribute(k_conv2d_mma, cudaFuncAttributeMaxDynamicSharedMemorySize, CONV_SMEM);

    k_stem<<<dim3(NN, NB), 128>>>(seq, conv1_w, conv2_w);
    k_pair0<<<C2TOT/256, 256>>>();

    int xs = 0;
    for (int l = 0; l < 3; ++l) {
        int rd   = l & 1;        // which buffer holds incoming c
        int cnew = rd ^ 1;       // buffer that will hold new c

        k_conv1bn<<<DIMD, 384>>>(rd, c1d_w + l*DIMD*DIMD*3, bn1_g + l*DIMD, bn1_b + l*DIMD);
        k_ln<<<dim3(NN, NB), DIMD>>>(xs, cnew, ln_g + l*DIMD, ln_b + l*DIMD);
        k_splitw<<<1152, 256>>>(c2d_w + l*C2C*C2C*9);
        k_conv2d_mma<<<dim3(4, NN, NB), 256, CONV_SMEM>>>(cnew);
        k_bnstats<<<C2C, 256>>>(bn2_g + l*C2C, bn2_b + l*C2C);
        k_bnapply<<<C2TOT/256, 256>>>();
        k_gate<<<dim3(NN, NB), NN>>>(wd_w + l*HH*C2C);
        k_gemm64<<<dim3(2, 6), 256>>>(xs, 0, wq_w + l*DIMD*DIMD, wq_b + l*DIMD, 0, nullptr);
        k_gemm64<<<dim3(2, 6), 256>>>(xs, 0, wk_w + l*DIMD*DIMD, wk_b + l*DIMD, 1, nullptr);
        k_gemm64<<<dim3(2, 6), 256>>>(xs, 0, wv_w + l*DIMD*DIMD, wv_b + l*DIMD, 2, nullptr);
        k_attn<<<dim3(NN, HH, NB), 256>>>(mask, wd_b + l*HH);
        k_gemm64<<<dim3(2, 6), 256>>>(xs, 1, wl_w + l*DIMD*DIMD, wl_b + l*DIMD, xs ? 3 : 4, nullptr);
        xs ^= 1;
    }
    k_gemm64<<<dim3(2, 6), 256>>>(xs, 0, fc_w, fc_b, 5, out);
}

// round 10
// speedup vs baseline: 3.6053x; 2.1634x over previous
#include <cuda_runtime.h>
#include <cuda_bf16.h>
#include <cstdint>

// ---------------- problem constants ----------------
#define NB   2
#define NN   192
#define IND  20
#define DIMD 128
#define HH   8
#define DHH  16
#define C2C  256
#define NSP  (NN*NN)            // 36864
#define C2TOT (NB*C2C*NSP)      // 18874368

// ---------------- scratch (device globals; no allocation allowed) ----------------
__device__ float g_xA[NB*NN*DIMD];
__device__ float g_xB[NB*NN*DIMD];
__device__ float g_cA[NB*DIMD*NN];
__device__ float g_cB[NB*DIMD*NN];
__device__ float g_q[NB*HH*NN*DHH];
__device__ float g_k[NB*HH*NN*DHH];
__device__ float g_v[NB*HH*NN*DHH];
__device__ float g_upd[NB*NN*DIMD];
__device__ float g_G[NB*HH*NSP];
__device__ float g_scale[C2C];
__device__ float g_shift[C2C];
__device__ float g_c2A[C2TOT];     // persistent pair state (post BN+relu)
__device__ float g_c2X[C2TOT];     // raw conv2d output (pre-BN)
// split conv2d weights, bf16 hi/lo packed (ic even | ic odd<<16)
// layout: [ocblk4][icc16][tap9][icpair8][oc64]
__device__ unsigned g_Wh[C2C*C2C*9/2];
__device__ unsigned g_Wl[C2C*C2C*9/2];
// pre-split conv2d INPUT (state + pair), bf16 hi/lo packed by ic-pair:
// layout: [b2][icpair128][row192][j192]  (u32 each)
#define BPTOT (NB*128*NN*NN)    // 9437184
__device__ unsigned g_Bh[BPTOT];
__device__ unsigned g_Bl[BPTOT];

// =================================================================
// Stem: x = conv1d(seq^T, conv1_w)^T ; c = conv1d(seq^T, conv2_w)
// =================================================================
__global__ void k_stem(const float* __restrict__ seq,
                       const float* __restrict__ w1,
                       const float* __restrict__ w2)
{
    int n = blockIdx.x, b = blockIdx.y, d = threadIdx.x;
    __shared__ float s3[3][IND];
    if (d < 3*IND) {
        int r = d / IND, ic = d % IND;
        int nn = n - 1 + r;
        s3[r][ic] = (nn >= 0 && nn < NN) ? seq[(b*NN + nn)*IND + ic] : 0.f;
    }
    __syncthreads();
    float ax = 0.f, ac = 0.f;
    #pragma unroll
    for (int ic = 0; ic < IND; ++ic) {
        #pragma unroll
        for (int r = 0; r < 3; ++r) {
            float v = s3[r][ic];
            ax += v * w1[(d*IND + ic)*3 + r];
            ac += v * w2[(d*IND + ic)*3 + r];
        }
    }
    g_xA[(b*NN + n)*DIMD + d] = ax;
    g_cA[(b*DIMD + d)*NN + n] = ac;
}

// =================================================================
// init pair state:  c2A = seq2pair(cA)
// =================================================================
__global__ void k_pair0()
{
    int idx = blockIdx.x * blockDim.x + threadIdx.x;
    int j  = idx % NN;
    int r1 = idx / NN;
    int i  = r1 % NN;
    int r2 = r1 / NN;
    int ch = r2 % C2C;
    int b  = r2 / C2C;
    float pv = (ch < DIMD) ? g_cA[(b*DIMD + ch)*NN + i]
                           : g_cA[(b*DIMD + (ch - DIMD))*NN + j];
    g_c2A[idx] = pv;
}

// =================================================================
// c = relu(bn1(conv1d(c, c1d_w[l])))  — chunked smem staging, 16 syncs.
// block = out channel d (128 blocks), 384 threads = (b,n).
// =================================================================
__global__ void __launch_bounds__(384)
k_conv1bn(int rd, const float* __restrict__ w,
          const float* __restrict__ gg, const float* __restrict__ bb)
{
    int d = blockIdx.x;
    int t = threadIdx.x;
    int b = t / NN, n = t % NN;
    const float* c  = rd ? g_cB : g_cA;
    float*       co = rd ? g_cA : g_cB;

    __shared__ float sc[16][2][194];
    __shared__ float wsh[DIMD*3];
    __shared__ float red[2][12];

    wsh[t] = w[d*DIMD*3 + t];                 // 384 == DIMD*3 exactly
    if (t < 32) { sc[t >> 1][t & 1][0] = 0.f; sc[t >> 1][t & 1][193] = 0.f; }
    __syncthreads();

    float acc = 0.f;
    for (int ec = 0; ec < DIMD; ec += 16) {
        #pragma unroll
        for (int q = 0; q < 16; ++q) {
            int s = q*384 + t;                 // 6144 = 16*2*192
            int e1 = s / 384;
            int rem = s - e1*384;
            int bb2 = rem / NN, n2 = rem - bb2*NN;
            sc[e1][bb2][n2 + 1] = c[((bb2*DIMD) + ec + e1)*NN + n2];
        }
        __syncthreads();
        #pragma unroll
        for (int e1 = 0; e1 < 16; ++e1) {
            int e = ec + e1;
            acc += sc[e1][b][n]     * wsh[e*3 + 0]
                 + sc[e1][b][n + 1] * wsh[e*3 + 1]
                 + sc[e1][b][n + 2] * wsh[e*3 + 2];
        }
        __syncthreads();
    }

    float s = acc, ss = acc * acc;
    #pragma unroll
    for (int o = 16; o; o >>= 1) {
        s  += __shfl_down_sync(0xffffffffu, s,  o);
        ss += __shfl_down_sync(0xffffffffu, ss, o);
    }
    if (!(t & 31)) { red[0][t >> 5] = s; red[1][t >> 5] = ss; }
    __syncthreads();
    float ts = 0.f, tss = 0.f;
    #pragma unroll
    for (int ww = 0; ww < 12; ++ww) { ts += red[0][ww]; tss += red[1][ww]; }
    float mean = ts * (1.f/384.f);
    float var  = tss * (1.f/384.f) - mean*mean;
    float inv  = rsqrtf(var + 1e-5f);

    float outv = (acc - mean) * inv * gg[d] + bb[d];
    co[(b*DIMD + d)*NN + n] = fmaxf(outv, 0.f);
}

// =================================================================
// x = LN(x + c^T)
// =================================================================
__global__ void k_ln(int xs, int cs,
                     const float* __restrict__ gg, const float* __restrict__ bb)
{
    int n = blockIdx.x, b = blockIdx.y, d = threadIdx.x;
    float*       x = xs ? g_xB : g_xA;
    const float* c = cs ? g_cB : g_cA;

    float v = x[(b*NN + n)*DIMD + d] + c[(b*DIMD + d)*NN + n];

    __shared__ float red[2][4];
    float s = v, ss = v*v;
    #pragma unroll
    for (int o = 16; o; o >>= 1) {
        s  += __shfl_down_sync(0xffffffffu, s,  o);
        ss += __shfl_down_sync(0xffffffffu, ss, o);
    }
    if (!(d & 31)) { red[0][d >> 5] = s; red[1][d >> 5] = ss; }
    __syncthreads();
    float m   = (red[0][0]+red[0][1]+red[0][2]+red[0][3]) * (1.f/128.f);
    float var = (red[1][0]+red[1][1]+red[1][2]+red[1][3]) * (1.f/128.f) - m*m;
    float inv = rsqrtf(var + 1e-5f);
    x[(b*NN + n)*DIMD + d] = (v - m) * inv * gg[d] + bb[d];
}

// =================================================================
// split conv2d weights -> bf16 hi/lo, packed pairs along ic.
// grid = 1152 x 256
// =================================================================
__global__ void k_splitw(const float* __restrict__ w)   // w: [256][256][9]
{
    int o = blockIdx.x * 256 + threadIdx.x;
    int oc    = o & 63;
    int p     = (o >> 6) & 7;
    int tap   = (o >> 9) % 9;
    int icc   = (o / 4608) & 15;
    int ocblk = o / 73728;
    int ocg = ocblk*64 + oc;
    int ic0 = icc*16 + 2*p;
    float x0 = w[(ocg*C2C + ic0    )*9 + tap];
    float x1 = w[(ocg*C2C + ic0 + 1)*9 + tap];
    __nv_bfloat16 h0 = __float2bfloat16(x0);
    __nv_bfloat16 h1 = __float2bfloat16(x1);
    __nv_bfloat16 l0 = __float2bfloat16(x0 - __bfloat162float(h0));
    __nv_bfloat16 l1 = __float2bfloat16(x1 - __bfloat162float(h1));
    g_Wh[o] = ((unsigned)__bfloat16_as_ushort(h1) << 16) | __bfloat16_as_ushort(h0);
    g_Wl[o] = ((unsigned)__bfloat16_as_ushort(l1) << 16) | __bfloat16_as_ushort(l0);
}

// =================================================================
// prep conv2d input: v = c2A + seq2pair(c_cur), split bf16 hi/lo,
// packed (ic even | ic odd<<16) at [b][icpair][row][j].
// grid 36864 x 256  (one thread per u32)
// =================================================================
__global__ void k_prep(int csel)
{
    int idx = blockIdx.x * 256 + threadIdx.x;      // 0..BPTOT-1
    int j   = idx % NN;
    int r1  = idx / NN;
    int row = r1 % NN;
    int r2  = r1 / NN;
    int icp = r2 % 128;
    int b   = r2 / 128;
    const float* cc = csel ? g_cB : g_cA;

    int ic0 = icp*2;
    float x0 = g_c2A[((size_t)(b*C2C + ic0    )*NN + row)*NN + j]
             + ((ic0     < DIMD) ? cc[(b*DIMD + ic0)*NN + row]
                                 : cc[(b*DIMD + ic0 - DIMD)*NN + j]);
    int ic1 = ic0 + 1;
    float x1 = g_c2A[((size_t)(b*C2C + ic1)*NN + row)*NN + j]
             + ((ic1 < DIMD) ? cc[(b*DIMD + ic1)*NN + row]
                             : cc[(b*DIMD + ic1 - DIMD)*NN + j]);

    __nv_bfloat16 h0 = __float2bfloat16(x0);
    __nv_bfloat16 h1 = __float2bfloat16(x1);
    __nv_bfloat16 l0 = __float2bfloat16(x0 - __bfloat162float(h0));
    __nv_bfloat16 l1 = __float2bfloat16(x1 - __bfloat162float(h1));
    g_Bh[idx] = ((unsigned)__bfloat16_as_ushort(h1) << 16) | __bfloat16_as_ushort(h0);
    g_Bl[idx] = ((unsigned)__bfloat16_as_ushort(l1) << 16) | __bfloat16_as_ushort(l0);
}

// =================================================================
// conv2d 3x3 C2->C2 on tensor cores (bf16 hi/lo split, mma.m16n8k16).
// Input pre-split in g_Bh/g_Bl.  Raw out -> g_c2X.
// CTA: 64 oc x output row i x batch.  8 warps: 32 oc x 48 j each.
// K loop: 16 chunks of 16 ic (8 icpairs); 9 taps per chunk.
// Smem (u32): Ah/Al [tap9][icpair8][oc stride 72]  (5184 each)
//             Bh/Bl [r3*icpair8][col stride 200]   (4800 each), data at col 4..195
// =================================================================
#define MMA_BF16(c0,c1,c2,c3, A0,A1,A2,A3, B0,B1)                         \
  asm volatile("mma.sync.aligned.m16n8k16.row.col.f32.bf16.bf16.f32 "     \
    "{%0,%1,%2,%3},{%4,%5,%6,%7},{%8,%9},{%0,%1,%2,%3};"                  \
    : "+f"(c0),"+f"(c1),"+f"(c2),"+f"(c3)                                 \
    : "r"(A0),"r"(A1),"r"(A2),"r"(A3),"r"(B0),"r"(B1))

#define ASZ 5184
#define BSZ 4800
#define CONV_SMEM ((2*ASZ + 2*BSZ)*4)   // 79872 B

__global__ void __launch_bounds__(256, 2)
k_conv2d_mma()
{
    extern __shared__ unsigned smu[];
    unsigned* Ah = smu;
    unsigned* Al = smu + ASZ;
    unsigned* Bh = smu + 2*ASZ;
    unsigned* Bl = smu + 2*ASZ + BSZ;

    int ocblk = blockIdx.x;       // 0..3
    int i     = blockIdx.y;       // 0..191
    int b     = blockIdx.z;       // 0..1
    int t = threadIdx.x;
    int w = t >> 5, lane = t & 31;
    int g = lane >> 2, tig = lane & 3;
    int wm = w & 1, wn = w >> 1;

    // zero B halo columns (cols 0..3 and 196..199 of 24 rows) — written once
    if (t < 192) {
        int rr = t / 8, cq = t & 7;            // 24 rows x 8 halo cols
        int col = (cq < 4) ? cq : (192 + cq);
        Bh[rr*200 + col] = 0u;
        Bl[rr*200 + col] = 0u;
    }

    float acc[2][6][4];
    #pragma unroll
    for (int m = 0; m < 2; ++m)
        #pragma unroll
        for (int u = 0; u < 6; ++u)
            #pragma unroll
            for (int q = 0; q < 4; ++q) acc[m][u][q] = 0.f;

    const unsigned* whsrc = g_Wh + ocblk*73728;
    const unsigned* wlsrc = g_Wl + ocblk*73728;

    for (int icc = 0; icc < 16; ++icc) {
        // ---- stage weights: 2 x 1152 uint4 (vectorized linear copy) ----
        #pragma unroll
        for (int q = 0; q < 9; ++q) {
            int sidx = q*256 + t;              // 0..2303
            int hl = sidx >= 1152;
            int s2 = hl ? sidx - 1152 : sidx;  // uint4 index within tile
            int s4 = s2 * 4;                   // element index
            int tap = s4 >> 9, p = (s4 >> 6) & 7, oc = s4 & 63;
            int dst = ((tap*8 + p)*72 + oc) >> 2;
            const uint4 v = ((const uint4*)(hl ? wlsrc : whsrc))[icc*1152 + s2];
            ((uint4*)(hl ? Al : Ah))[dst] = v;
        }
        // ---- stage input: 2 x 24 segs x 48 uint4 from presplit global ----
        #pragma unroll
        for (int q = 0; q < 9; ++q) {
            int sidx = q*256 + t;              // 0..2303
            int hl = sidx >= 1152;
            int s2 = hl ? sidx - 1152 : sidx;
            int seg = s2 / 48, v4 = s2 - seg*48;   // seg = r*8+icp
            int r = seg >> 3, icp = seg & 7;
            int row = i - 1 + r;
            uint4 val = make_uint4(0u,0u,0u,0u);
            if (row >= 0 && row < NN)
                val = ((const uint4*)(hl ? g_Bl : g_Bh))
                        [(size_t)((b*128 + icc*8 + icp)*NN + row)*48 + v4];
            ((uint4*)(hl ? Bl : Bh))[(seg*200 + 4 + v4*4) >> 2] = val;
        }
        __syncthreads();

        #pragma unroll
        for (int r = 0; r < 3; ++r) {
            #pragma unroll
            for (int dj = 0; dj < 3; ++dj) {
                int tap = r*3 + dj;
                unsigned ah[2][4], al[2][4];
                #pragma unroll
                for (int m = 0; m < 2; ++m) {
                    int mb = wm*32 + m*16 + g;
                    ah[m][0] = Ah[(tap*8 + tig    )*72 + mb    ];
                    ah[m][1] = Ah[(tap*8 + tig    )*72 + mb + 8];
                    ah[m][2] = Ah[(tap*8 + tig + 4)*72 + mb    ];
                    ah[m][3] = Ah[(tap*8 + tig + 4)*72 + mb + 8];
                    al[m][0] = Al[(tap*8 + tig    )*72 + mb    ];
                    al[m][1] = Al[(tap*8 + tig    )*72 + mb + 8];
                    al[m][2] = Al[(tap*8 + tig + 4)*72 + mb    ];
                    al[m][3] = Al[(tap*8 + tig + 4)*72 + mb + 8];
                }
                #pragma unroll
                for (int u = 0; u < 6; ++u) {
                    int col = wn*48 + u*8 + g + dj + 3;   // data offset 4, shift -1
                    unsigned bh0 = Bh[(r*8 + tig    )*200 + col];
                    unsigned bh1 = Bh[(r*8 + tig + 4)*200 + col];
                    unsigned bl0 = Bl[(r*8 + tig    )*200 + col];
                    unsigned bl1 = Bl[(r*8 + tig + 4)*200 + col];
                    #pragma unroll
                    for (int m = 0; m < 2; ++m) {
                        float* c = acc[m][u];
                        MMA_BF16(c[0],c[1],c[2],c[3],
                                 ah[m][0],ah[m][1],ah[m][2],ah[m][3], bh0,bh1);
                        MMA_BF16(c[0],c[1],c[2],c[3],
                                 ah[m][0],ah[m][1],ah[m][2],ah[m][3], bl0,bl1);
                        MMA_BF16(c[0],c[1],c[2],c[3],
                                 al[m][0],al[m][1],al[m][2],al[m][3], bh0,bh1);
                    }
                }
            }
        }
        __syncthreads();
    }

    // ---- epilogue: raw conv output to g_c2X ----
    #pragma unroll
    for (int m = 0; m < 2; ++m) {
        int oc0 = ocblk*64 + wm*32 + m*16 + g;
        #pragma unroll
        for (int u = 0; u < 6; ++u) {
            int j = wn*48 + u*8 + 2*tig;
            *(float2*)&g_c2X[((size_t)(b*C2C + oc0    )*NN + i)*NN + j] =
                make_float2(acc[m][u][0], acc[m][u][1]);
            *(float2*)&g_c2X[((size_t)(b*C2C + oc0 + 8)*NN + i)*NN + j] =
                make_float2(acc[m][u][2], acc[m][u][3]);
        }
    }
}

// =================================================================
// BN2 stats on raw conv output g_c2X
// =================================================================
__global__ void k_bnstats(const float* __restrict__ gg, const float* __restrict__ bb)
{
    int oc = blockIdx.x, t = threadIdx.x;
    float s = 0.f, ss = 0.f;
    for (int b = 0; b < NB; ++b) {
        const float* p = g_c2X + (size_t)(b*C2C + oc)*NSP;
        for (int k = t; k < NSP; k += 256) {
            float v = p[k];
            s += v; ss += v*v;
        }
    }
    __shared__ float red[2][8];
    #pragma unroll
    for (int o = 16; o; o >>= 1) {
        s  += __shfl_down_sync(0xffffffffu, s,  o);
        ss += __shfl_down_sync(0xffffffffu, ss, o);
    }
    if (!(t & 31)) { red[0][t >> 5] = s; red[1][t >> 5] = ss; }
    __syncthreads();
    if (t == 0) {
        float ts = 0.f, tss = 0.f;
        #pragma unroll
        for (int ww = 0; ww < 8; ++ww) { ts += red[0][ww]; tss += red[1][ww]; }
        float mean = ts * (1.f / (NB*NSP));
        float var  = tss * (1.f / (NB*NSP)) - mean*mean;
        float inv  = rsqrtf(var + 1e-5f);
        float sc = inv * gg[oc];
        g_scale[oc] = sc;
        g_shift[oc] = bb[oc] - mean * sc;
    }
}

// bnapply: state update  c2A = relu(bn(c2X))
__global__ void k_bnapply()
{
    int idx = blockIdx.x * blockDim.x + threadIdx.x;
    int oc = (idx / NSP) % C2C;
    float v = g_c2X[idx];
    g_c2A[idx] = fmaxf(v * g_scale[oc] + g_shift[oc], 0.f);
}

// =================================================================
// gate logits: G[b,h,i,j] = sum_c c2A[b,c,i,j] * wd[h,c]
// =================================================================
__global__ void k_gate(const float* __restrict__ wd)
{
    int i = blockIdx.x, b = blockIdx.y, j = threadIdx.x;
    __shared__ float wsh[C2C*HH];
    for (int s = j; s < C2C*HH; s += NN) {
        int c = s >> 3, h = s & 7;
        wsh[s] = wd[h*C2C + c];
    }
    __syncthreads();
    float acc[HH] = {};
    const float* base = g_c2A + (size_t)(b*C2C)*NSP + i*NN + j;
    #pragma unroll 4
    for (int c = 0; c < C2C; ++c) {
        float v = base[(size_t)c*NSP];
        #pragma unroll
        for (int h = 0; h < HH; ++h) acc[h] += v * wsh[c*8 + h];
    }
    #pragma unroll
    for (int h = 0; h < HH; ++h)
        g_G[((b*HH + h)*NN + i)*NN + j] = acc[h];
}

// =================================================================
// Generic 384x128x128 GEMM with relu epilogue.
// =================================================================
__global__ void k_gemm64(int asel, int addupd,
                         const float* __restrict__ W,
                         const float* __restrict__ bias,
                         int outsel, float* dptr)
{
    __shared__ float As[32*68];
    __shared__ float Ws[32*68];
    int t = threadIdx.x;
    int tx = t & 15, ty = t >> 4;
    int rowbase = blockIdx.y * 64, colbase = blockIdx.x * 64;

    const float* A = asel ? g_xB : g_xA;
    float* outp; int headed = 0;
    if      (outsel == 0) { outp = g_q; headed = 1; }
    else if (outsel == 1) { outp = g_k; headed = 1; }
    else if (outsel == 2) { outp = g_v; headed = 1; }
    else if (outsel == 3) { outp = g_xA; }
    else if (outsel == 4) { outp = g_xB; }
    else                  { outp = dptr; }

    float acc[4][4] = {};
    for (int kk = 0; kk < 128; kk += 32) {
        #pragma unroll
        for (int r = 0; r < 8; ++r) {
            int s = r*256 + t;
            int row = s >> 5, e = s & 31;
            float v = A[(rowbase + row)*DIMD + kk + e];
            if (addupd) v += g_upd[(rowbase + row)*DIMD + kk + e];
            As[e*68 + row] = v;
            Ws[e*68 + row] = W[(colbase + row)*DIMD + kk + e];
        }
        __syncthreads();
        #pragma unroll
        for (int e = 0; e < 32; ++e) {
            float a0 = As[e*68 + ty*4 + 0], a1 = As[e*68 + ty*4 + 1];
            float a2 = As[e*68 + ty*4 + 2], a3 = As[e*68 + ty*4 + 3];
            float w0 = Ws[e*68 + tx*4 + 0], w1 = Ws[e*68 + tx*4 + 1];
            float w2 = Ws[e*68 + tx*4 + 2], w3 = Ws[e*68 + tx*4 + 3];
            acc[0][0] += a0*w0; acc[0][1] += a0*w1; acc[0][2] += a0*w2; acc[0][3] += a0*w3;
            acc[1][0] += a1*w0; acc[1][1] += a1*w1; acc[1][2] += a1*w2; acc[1][3] += a1*w3;
            acc[2][0] += a2*w0; acc[2][1] += a2*w1; acc[2][2] += a2*w2; acc[2][3] += a2*w3;
            acc[3][0] += a3*w0; acc[3][1] += a3*w1; acc[3][2] += a3*w2; acc[3][3] += a3*w3;
        }
        __syncthreads();
    }

    #pragma unroll
    for (int v = 0; v < 4; ++v) {
        int row = rowbase + ty*4 + v;
        #pragma unroll
        for (int u = 0; u < 4; ++u) {
            int col = colbase + tx*4 + u;
            float r = fmaxf(acc[v][u] + bias[col], 0.f);
            if (headed) {
                int b = row / NN, n = row % NN, h = col >> 4, dh = col & 15;
                outp[((b*HH + h)*NN + n)*DHH + dh] = r;
            } else {
                outp[row*DIMD + col] = r;
            }
        }
    }
}

// =================================================================
// Attention + gate
// =================================================================
__global__ void k_attn(const float* __restrict__ mask,
                       const float* __restrict__ wdb)
{
    int i = blockIdx.x, h = blockIdx.y, b = blockIdx.z;
    int t = threadIdx.x;
    int bh = b*HH + h;

    __shared__ float qi[DHH];
    __shared__ float att[NN];
    __shared__ float redm[8];
    __shared__ float reds[8];
    __shared__ float part[16][17];

    if (t < DHH) qi[t] = g_q[(bh*NN + i)*DHH + t];
    __syncthreads();

    float aval = 0.f;
    if (t < NN) {
        const float* kp = g_k + (bh*NN + t)*DHH;
        float s = 0.f;
        #pragma unroll
        for (int d = 0; d < DHH; ++d) s += qi[d] * kp[d];
        aval = s * 0.25f;
    }
    float mval = (t < NN) ? aval : -3e38f;
    #pragma unroll
    for (int o = 16; o; o >>= 1) mval = fmaxf(mval, __shfl_xor_sync(0xffffffffu, mval, o));
    if (!(t & 31)) redm[t >> 5] = mval;
    __syncthreads();
    float mx = redm[0];
    #pragma unroll
    for (int ww = 1; ww < 8; ++ww) mx = fmaxf(mx, redm[ww]);

    float e = (t < NN) ? expf(aval - mx) * mask[b*NN + t] : 0.f;
    float sv = e;
    #pragma unroll
    for (int o = 16; o; o >>= 1) sv += __shfl_xor_sync(0xffffffffu, sv, o);
    if (!(t & 31)) reds[t >> 5] = sv;
    __syncthreads();
    float den = 1e-6f;
    #pragma unroll
    for (int ww = 0; ww < 8; ++ww) den += reds[ww];

    if (t < NN) {
        float gl = g_G[(bh*NN + i)*NN + t] + g_G[(bh*NN + t)*NN + i] + wdb[h];
        float gate = 1.f / (1.f + expf(-gl));
        att[t] = (e / den) * gate;
    }
    __syncthreads();

    int d = t & 15, grp = t >> 4;
    float p = 0.f;
    #pragma unroll
    for (int jj = 0; jj < 12; ++jj) {
        int j = grp*12 + jj;
        p += att[j] * g_v[(bh*NN + j)*DHH + d];
    }
    part[grp][d] = p;
    __syncthreads();
    if (t < DHH) {
        float s = 0.f;
        #pragma unroll
        for (int gg = 0; gg < 16; ++gg) s += part[gg][t];
        g_upd[(b*NN + i)*DIMD + h*DHH + t] = s;
    }
}

// =================================================================
// host
// =================================================================
extern "C" void kernel_launch(void* const* d_in, const int* in_sizes, int n_in,
                              void* d_out, int out_size)
{
    const float* seq     = (const float*)d_in[0];
    const float* mask    = (const float*)d_in[1];
    const float* conv1_w = (const float*)d_in[2];
    const float* conv2_w = (const float*)d_in[3];
    const float* ln_g    = (const float*)d_in[4];
    const float* ln_b    = (const float*)d_in[5];
    const float* c1d_w   = (const float*)d_in[6];
    const float* bn1_g   = (const float*)d_in[7];
    const float* bn1_b   = (const float*)d_in[8];
    const float* c2d_w   = (const float*)d_in[9];
    const float* bn2_g   = (const float*)d_in[10];
    const float* bn2_b   = (const float*)d_in[11];
    const float* wq_w    = (const float*)d_in[12];
    const float* wq_b    = (const float*)d_in[13];
    const float* wk_w    = (const float*)d_in[14];
    const float* wk_b    = (const float*)d_in[15];
    const float* wv_w    = (const float*)d_in[16];
    const float* wv_b    = (const float*)d_in[17];
    const float* wd_w    = (const float*)d_in[18];
    const float* wd_b    = (const float*)d_in[19];
    const float* wl_w    = (const float*)d_in[20];
    const float* wl_b    = (const float*)d_in[21];
    const float* fc_w    = (const float*)d_in[22];
    const float* fc_b    = (const float*)d_in[23];
    float* out = (float*)d_out;

    static int smem_set = 0;
    if (!smem_set) {
        cudaFuncSetAttribute(k_conv2d_mma, cudaFuncAttributeMaxDynamicSharedMemorySize, CONV_SMEM);
        smem_set = 1;
    }

    k_stem<<<dim3(NN, NB), 128>>>(seq, conv1_w, conv2_w);
    k_pair0<<<C2TOT/256, 256>>>();

    int xs = 0;
    for (int l = 0; l < 3; ++l) {
        int rd   = l & 1;        // which buffer holds incoming c
        int cnew = rd ^ 1;       // buffer that will hold new c

        k_conv1bn<<<DIMD, 384>>>(rd, c1d_w + l*DIMD*DIMD*3, bn1_g + l*DIMD, bn1_b + l*DIMD);
        k_ln<<<dim3(NN, NB), DIMD>>>(xs, cnew, ln_g + l*DIMD, ln_b + l*DIMD);
        k_splitw<<<1152, 256>>>(c2d_w + l*C2C*C2C*9);
        k_prep<<<BPTOT/256, 256>>>(cnew);
        k_conv2d_mma<<<dim3(4, NN, NB), 256, CONV_SMEM>>>();
        k_bnstats<<<C2C, 256>>>(bn2_g + l*C2C, bn2_b + l*C2C);
        k_bnapply<<<C2TOT/256, 256>>>();
        k_gate<<<dim3(NN, NB), NN>>>(wd_w + l*HH*C2C);
        k_gemm64<<<dim3(2, 6), 256>>>(xs, 0, wq_w + l*DIMD*DIMD, wq_b + l*DIMD, 0, nullptr);
        k_gemm64<<<dim3(2, 6), 256>>>(xs, 0, wk_w + l*DIMD*DIMD, wk_b + l*DIMD, 1, nullptr);
        k_gemm64<<<dim3(2, 6), 256>>>(xs, 0, wv_w + l*DIMD*DIMD, wv_b + l*DIMD, 2, nullptr);
        k_attn<<<dim3(NN, HH, NB), 256>>>(mask, wd_b + l*HH);
        k_gemm64<<<dim3(2, 6), 256>>>(xs, 1, wl_w + l*DIMD*DIMD, wl_b + l*DIMD, xs ? 3 : 4, nullptr);
        xs ^= 1;
    }
    k_gemm64<<<dim3(2, 6), 256>>>(xs, 0, fc_w, fc_b, 5, out);
}